// round 5
// baseline (speedup 1.0000x reference)
#include <cuda_runtime.h>

#define NN   100000
#define EE   800000
#define D    64
#define CD   256          // (HOPS+1)*D
#define NG   64
#define EMBD 128
#define PB   512          // persistent blocks (co-resident: 148 SMs x 4)
#define CH   196          // nodes per prep block chunk (512*196 >= NN)
#define HOPSLOTS (PB * 16)

// Persistent scratch
__device__ float d_F[(size_t)NN * CD];   // concat features [N][256]
__device__ int   d_cnt[NN];
__device__ int   d_cur[NN];
__device__ int   d_off[NN + 1];
__device__ int   d_csr[EE];
__device__ int   d_bsum[PB];
__device__ float d_dn[NN];
__device__ float d_gsum[NG * D];
__device__ int   d_bar_cnt = 0;
__device__ int   d_bar_gen = 0;

// ---------------------------------------------------------------------------
// Packed fp32x2 (Blackwell FFMA2)
__device__ __forceinline__ unsigned long long pk2(float x, float y) {
    unsigned long long r;
    asm("mov.b64 %0, {%1,%2};" : "=l"(r) : "f"(x), "f"(y));
    return r;
}
__device__ __forceinline__ void upk2(unsigned long long v, float& lo, float& hi) {
    asm("mov.b64 {%0,%1}, %2;" : "=f"(lo), "=f"(hi) : "l"(v));
}
__device__ __forceinline__ void ffma2(unsigned long long& d, unsigned long long a,
                                      unsigned long long b) {
    asm("fma.rn.f32x2 %0, %1, %2, %0;" : "+l"(d) : "l"(a), "l"(b));
}

// ---------------------------------------------------------------------------
// Software grid barrier; ALL nblk blocks must be co-resident.
__device__ __forceinline__ void gbar(int nblk) {
    __threadfence();
    __syncthreads();
    if (threadIdx.x == 0) {
        int g = *((volatile int*)&d_bar_gen);
        int r = atomicAdd(&d_bar_cnt, 1);
        if (r == nblk - 1) {
            d_bar_cnt = 0;
            __threadfence();
            atomicAdd(&d_bar_gen, 1);
        } else {
            while (*((volatile int*)&d_bar_gen) == g) {}
        }
    }
    __syncthreads();
}

// ---------------------------------------------------------------------------
// prepA: zero counters/gsum + copy h into F slot0
__global__ void k_prepA(const float* __restrict__ h) {
    int i = blockIdx.x * blockDim.x + threadIdx.x;      // grid covers NN*16
    if (i < NN * 16) {
        int r = i >> 4, p = i & 15;
        ((float4*)d_F)[(size_t)r * 64 + p] = ((const float4*)h)[i];
    }
    if (i < NN) { d_cnt[i] = 0; d_cur[i] = 0; }
    if (i < NG * D) d_gsum[i] = 0.f;
}

// prepB (persistent): count -> scan(off,dn) -> CSR fill
__global__ void __launch_bounds__(256, 4) k_prepB(const int* __restrict__ src,
                                                  const int* __restrict__ dst) {
    __shared__ int sh[256];
    int tid = threadIdx.x, b = blockIdx.x;
    int gt = b * 256 + tid;
    const int GS = PB * 256;

    // P1: in-degree count
    for (int e = gt; e < EE; e += GS) atomicAdd(&d_cnt[dst[e]], 1);
    gbar(PB);

    // P2: per-block chunk sums
    {
        int i0 = b * CH;
        int v = 0;
        if (tid < CH && i0 + tid < NN) v = d_cnt[i0 + tid];
        sh[tid] = v;
        __syncthreads();
        for (int st = 128; st > 0; st >>= 1) {
            if (tid < st) sh[tid] += sh[tid + st];
            __syncthreads();
        }
        if (tid == 0) d_bsum[b] = sh[0];
    }
    gbar(PB);

    // P3: exclusive prefix (off) + deg_norm
    {
        int part = 0;
        for (int i = tid; i < b; i += 256) part += d_bsum[i];
        sh[tid] = part;
        __syncthreads();
        for (int st = 128; st > 0; st >>= 1) {
            if (tid < st) sh[tid] += sh[tid + st];
            __syncthreads();
        }
        int base = sh[0];
        __syncthreads();

        int i0 = b * CH, idx = i0 + tid;
        int v = (tid < CH && idx < NN) ? d_cnt[idx] : 0;
        sh[tid] = v;
        __syncthreads();
        for (int st = 1; st < 256; st <<= 1) {           // inclusive scan
            int a = (tid >= st) ? sh[tid - st] : 0;
            __syncthreads();
            sh[tid] += a;
            __syncthreads();
        }
        if (tid < CH && idx < NN) {
            d_off[idx] = base + sh[tid] - v;
            d_dn[idx] = rsqrtf(fmaxf((float)v, 1.0f));
        }
        if (gt == 0) d_off[NN] = EE;
    }
    gbar(PB);

    // P4: CSR fill
    for (int e = gt; e < EE; e += GS) {
        int dd = dst[e];
        int p = atomicAdd(&d_cur[dd], 1);
        d_csr[d_off[dd] + p] = src[e];
    }
}

// ---------------------------------------------------------------------------
// Persistent 3-hop kernel: half-warp (16 lanes x float4) per node; 4-edge
// software pipeline (MLP=4); grid barrier between hops.
__global__ void __launch_bounds__(256, 4) k_hops3() {
    int grp = threadIdx.x >> 4;
    int lane = threadIdx.x & 15;
    const float4* F4 = (const float4*)d_F;

    for (int hop = 1; hop <= 3; hop++) {
        int slot_in = (hop - 1) * 16 + lane;
        for (int node = blockIdx.x * 16 + grp; node < NN; node += HOPSLOTS) {
            int e0 = __ldg(d_off + node);
            int e1 = __ldg(d_off + node + 1);
            float4 acc = make_float4(0.f, 0.f, 0.f, 0.f);
            int e = e0;
            for (; e + 4 <= e1; e += 4) {
                int s0 = __ldg(d_csr + e);
                int s1 = __ldg(d_csr + e + 1);
                int s2 = __ldg(d_csr + e + 2);
                int s3 = __ldg(d_csr + e + 3);
                float w0 = __ldg(d_dn + s0);
                float w1 = __ldg(d_dn + s1);
                float w2 = __ldg(d_dn + s2);
                float w3 = __ldg(d_dn + s3);
                float4 v0 = __ldg(F4 + (size_t)s0 * 64 + slot_in);
                float4 v1 = __ldg(F4 + (size_t)s1 * 64 + slot_in);
                float4 v2 = __ldg(F4 + (size_t)s2 * 64 + slot_in);
                float4 v3 = __ldg(F4 + (size_t)s3 * 64 + slot_in);
                acc.x = fmaf(v0.x, w0, acc.x); acc.y = fmaf(v0.y, w0, acc.y);
                acc.z = fmaf(v0.z, w0, acc.z); acc.w = fmaf(v0.w, w0, acc.w);
                acc.x = fmaf(v1.x, w1, acc.x); acc.y = fmaf(v1.y, w1, acc.y);
                acc.z = fmaf(v1.z, w1, acc.z); acc.w = fmaf(v1.w, w1, acc.w);
                acc.x = fmaf(v2.x, w2, acc.x); acc.y = fmaf(v2.y, w2, acc.y);
                acc.z = fmaf(v2.z, w2, acc.z); acc.w = fmaf(v2.w, w2, acc.w);
                acc.x = fmaf(v3.x, w3, acc.x); acc.y = fmaf(v3.y, w3, acc.y);
                acc.z = fmaf(v3.z, w3, acc.z); acc.w = fmaf(v3.w, w3, acc.w);
            }
            for (; e < e1; e++) {
                int s = __ldg(d_csr + e);
                float w = __ldg(d_dn + s);
                float4 v = __ldg(F4 + (size_t)s * 64 + slot_in);
                acc.x = fmaf(v.x, w, acc.x); acc.y = fmaf(v.y, w, acc.y);
                acc.z = fmaf(v.z, w, acc.z); acc.w = fmaf(v.w, w, acc.w);
            }
            float dn = __ldg(d_dn + node);
            acc.x *= dn; acc.y *= dn; acc.z *= dn; acc.w *= dn;
            ((float4*)d_F)[(size_t)node * 64 + hop * 16 + lane] = acc;
        }
        if (hop < 3) gbar(PB);
    }
}

// ---------------------------------------------------------------------------
// GEMM: 256 threads; thread owns 2 nodes x 16 cols. W staged in two 32KB
// smem chunks (128 k-rows each); packed W pairs come from ulonglong2 LDS.128.
// out[n][c] = relu(F[n][0:256] @ W + b) -> F slot0
__global__ void __launch_bounds__(256) k_gemm(const float* __restrict__ W,
                                              const float* __restrict__ b) {
    __shared__ float Ws[128 * 64];     // 32KB chunk (128 k-rows x 64 cols)
    int tid = threadIdx.x;
    int trow = tid >> 2;               // 0..63
    int tcol = tid & 3;                // col chunk: tcol*16 .. +15
    int n0 = blockIdx.x * 128 + trow;
    int n1 = n0 + 64;
    bool ok0 = (n0 < NN), ok1 = (n1 < NN);

    const float4* rowA = (const float4*)(d_F + (size_t)n0 * CD);
    const float4* rowB = (const float4*)(d_F + (size_t)n1 * CD);
    const ulonglong2* Ws2 = (const ulonglong2*)Ws;   // 16B granules

    unsigned long long accA[8], accB[8];
#pragma unroll
    for (int p = 0; p < 8; p++) { accA[p] = 0ull; accB[p] = 0ull; }

    for (int kc = 0; kc < 2; kc++) {
        __syncthreads();
        for (int i = tid; i < 2048; i += 256)
            ((float4*)Ws)[i] = __ldg((const float4*)W + kc * 2048 + i);
        __syncthreads();

        for (int k4 = 0; k4 < 32; k4++) {
            float4 xa = ok0 ? __ldg(rowA + kc * 32 + k4) : make_float4(0.f, 0.f, 0.f, 0.f);
            float4 xb = ok1 ? __ldg(rowB + kc * 32 + k4) : make_float4(0.f, 0.f, 0.f, 0.f);
#pragma unroll
            for (int jj = 0; jj < 4; jj++) {
                float a = (jj == 0) ? xa.x : (jj == 1) ? xa.y : (jj == 2) ? xa.z : xa.w;
                float c = (jj == 0) ? xb.x : (jj == 1) ? xb.y : (jj == 2) ? xb.z : xb.w;
                unsigned long long xpA = pk2(a, a);
                unsigned long long xpB = pk2(c, c);
                int wbase = (k4 * 4 + jj) * 16 + tcol * 4;   // ulonglong2 index
#pragma unroll
                for (int q = 0; q < 4; q++) {
                    ulonglong2 wv = Ws2[wbase + q];          // LDS.128 -> 2 pairs
                    ffma2(accA[2 * q + 0], xpA, wv.x);
                    ffma2(accA[2 * q + 1], xpA, wv.y);
                    ffma2(accB[2 * q + 0], xpB, wv.x);
                    ffma2(accB[2 * q + 1], xpB, wv.y);
                }
            }
        }
    }

    __syncthreads();    // all X reads done before in-place slot0 writes

    float4 b0 = __ldg((const float4*)b + tcol * 4 + 0);
    float4 b1 = __ldg((const float4*)b + tcol * 4 + 1);
    float4 b2 = __ldg((const float4*)b + tcol * 4 + 2);
    float4 b3 = __ldg((const float4*)b + tcol * 4 + 3);
    float bias[16] = {b0.x, b0.y, b0.z, b0.w, b1.x, b1.y, b1.z, b1.w,
                      b2.x, b2.y, b2.z, b2.w, b3.x, b3.y, b3.z, b3.w};

    if (ok0) {
        float* orow = d_F + (size_t)n0 * CD + tcol * 16;
#pragma unroll
        for (int q = 0; q < 4; q++) {
            float o0, o1, o2, o3;
            upk2(accA[2 * q + 0], o0, o1);
            upk2(accA[2 * q + 1], o2, o3);
            float4 o;
            o.x = fmaxf(o0 + bias[4 * q + 0], 0.f);
            o.y = fmaxf(o1 + bias[4 * q + 1], 0.f);
            o.z = fmaxf(o2 + bias[4 * q + 2], 0.f);
            o.w = fmaxf(o3 + bias[4 * q + 3], 0.f);
            ((float4*)orow)[q] = o;
        }
    }
    if (ok1) {
        float* orow = d_F + (size_t)n1 * CD + tcol * 16;
#pragma unroll
        for (int q = 0; q < 4; q++) {
            float o0, o1, o2, o3;
            upk2(accB[2 * q + 0], o0, o1);
            upk2(accB[2 * q + 1], o2, o3);
            float4 o;
            o.x = fmaxf(o0 + bias[4 * q + 0], 0.f);
            o.y = fmaxf(o1 + bias[4 * q + 1], 0.f);
            o.z = fmaxf(o2 + bias[4 * q + 2], 0.f);
            o.w = fmaxf(o3 + bias[4 * q + 3], 0.f);
            ((float4*)orow)[q] = o;
        }
    }
}

// ---------------------------------------------------------------------------
// Per-graph sums of F slot0 (graph_ids sorted -> running-accumulator flush)
__global__ void k_gsum(const int* __restrict__ gid) {
    const int CHN = 512;
    int c = threadIdx.x & 63;
    int r0 = threadIdx.x >> 6;
    int nbeg = blockIdx.x * CHN + r0;
    int nend = min(NN, blockIdx.x * CHN + CHN);
    float acc = 0.f;
    int cur = -1;
    for (int n = nbeg; n < nend; n += 4) {
        int g = gid[n];
        if (g != cur) {
            if (cur >= 0) atomicAdd(&d_gsum[cur * D + c], acc);
            cur = g; acc = 0.f;
        }
        acc += d_F[(size_t)n * CD + c];
    }
    if (cur >= 0) atomicAdd(&d_gsum[cur * D + c], acc);
}

// Readout: mean -> @embW + embb -> L2 normalize.
__global__ void k_final(const int* __restrict__ gid,
                        const float* __restrict__ embW,
                        const float* __restrict__ embb,
                        float* __restrict__ out) {
    __shared__ float hg[NG][D];
    __shared__ int bnd[NG + 1];
    __shared__ float nrm[NG];
    int tid = threadIdx.x;

    if (tid <= NG) {
        int lo = 0, hi = NN;
        while (lo < hi) {
            int mid = (lo + hi) >> 1;
            if (gid[mid] < tid) lo = mid + 1; else hi = mid;
        }
        bnd[tid] = lo;
    }
    if (tid < NG) nrm[tid] = 0.f;
    __syncthreads();

    for (int idx = tid; idx < NG * D; idx += 128) {
        int g = idx >> 6;
        float cnt = (float)max(bnd[g + 1] - bnd[g], 1);
        hg[g][idx & 63] = d_gsum[idx] / cnt;
    }
    __syncthreads();

    for (int idx = tid; idx < NG * EMBD; idx += 128) {
        int g = idx >> 7, e = idx & 127;
        float s = embb[e];
#pragma unroll 16
        for (int k = 0; k < D; k++) s += hg[g][k] * embW[k * EMBD + e];
        atomicAdd(&nrm[g], s * s);
    }
    __syncthreads();

    for (int idx = tid; idx < NG * EMBD; idx += 128) {
        int g = idx >> 7, e = idx & 127;
        float s = embb[e];
#pragma unroll 16
        for (int k = 0; k < D; k++) s += hg[g][k] * embW[k * EMBD + e];
        float nv = fmaxf(sqrtf(nrm[g]), 1e-12f);
        out[idx] = s / nv;
    }
}

// ---------------------------------------------------------------------------
extern "C" void kernel_launch(void* const* d_in, const int* in_sizes, int n_in,
                              void* d_out, int out_size) {
    const float* h    = (const float*)d_in[0];
    const int*   src  = (const int*)d_in[1];
    const int*   dst  = (const int*)d_in[2];
    const int*   gid  = (const int*)d_in[3];
    const float* Wl[3] = {(const float*)d_in[4], (const float*)d_in[6], (const float*)d_in[8]};
    const float* bl[3] = {(const float*)d_in[5], (const float*)d_in[7], (const float*)d_in[9]};
    const float* embW = (const float*)d_in[10];
    const float* embb = (const float*)d_in[11];
    float* out = (float*)d_out;
    (void)in_sizes; (void)n_in; (void)out_size;

    k_prepA<<<(NN * 16 + 255) / 256, 256>>>(h);          // launch 1
    k_prepB<<<PB, 256>>>(src, dst);                      // launch 2

    for (int L = 0; L < 3; L++) {
        k_hops3<<<PB, 256>>>();                          // launch 3 (L=0)
        k_gemm<<<(NN + 127) / 128, 256>>>(Wl[L], bl[L]); // launch 4 (L=0) <- profiled
    }

    k_gsum<<<(NN + 511) / 512, 256>>>(gid);
    k_final<<<1, 128>>>(gid, embW, embb, out);
}

// round 7
// speedup vs baseline: 1.2677x; 1.2677x over previous
#include <cuda_runtime.h>

#define NN   100000
#define EE   800000
#define D    64
#define CD   256          // (HOPS+1)*D
#define NG   64
#define EMBD 128
#define PB   512          // persistent blocks for prepB
#define CH   196          // nodes per prep block chunk (512*196 >= NN)

// Persistent scratch
__device__ float d_F[(size_t)NN * CD];   // concat features [N][256]
__device__ float d_Wt[3 * 16384];        // permuted weights [L][kq][c][4]
__device__ int   d_cnt[NN];
__device__ int   d_cur[NN];
__device__ int   d_off[NN + 1];
__device__ int   d_csr[EE];
__device__ int   d_bsum[PB];
__device__ float d_dn[NN];
__device__ float d_gsum[NG * D];
__device__ int   d_bar_cnt = 0;
__device__ int   d_bar_gen = 0;

// ---------------------------------------------------------------------------
__device__ __forceinline__ void upk2(unsigned long long v, float& lo, float& hi) {
    asm("mov.b64 {%0,%1}, %2;" : "=f"(lo), "=f"(hi) : "l"(v));
}
__device__ __forceinline__ void ffma2(unsigned long long& d, unsigned long long a,
                                      unsigned long long b) {
    asm("fma.rn.f32x2 %0, %1, %2, %0;" : "+l"(d) : "l"(a), "l"(b));
}

// Software grid barrier; all nblk blocks co-resident.
__device__ __forceinline__ void gbar(int nblk) {
    __threadfence();
    __syncthreads();
    if (threadIdx.x == 0) {
        int g = *((volatile int*)&d_bar_gen);
        int r = atomicAdd(&d_bar_cnt, 1);
        if (r == nblk - 1) {
            d_bar_cnt = 0;
            __threadfence();
            atomicAdd(&d_bar_gen, 1);
        } else {
            while (*((volatile int*)&d_bar_gen) == g) {}
        }
    }
    __syncthreads();
}

// ---------------------------------------------------------------------------
// prepWt: permute all 3 W matrices into [kq][c][4k] layout for the GEMM.
__global__ void k_prepWt(const float* __restrict__ W0, const float* __restrict__ W1,
                         const float* __restrict__ W2) {
    int i = blockIdx.x * blockDim.x + threadIdx.x;
    if (i < 3 * 16384) {
        int L = i / 16384, gi = i - L * 16384;
        int kq = gi >> 8, r = gi & 255;
        int c = r >> 2, kk = r & 3;
        const float* W = (L == 0) ? W0 : (L == 1) ? W1 : W2;
        d_Wt[i] = W[(kq * 4 + kk) * 64 + c];
    }
}

// prepA: zero counters/gsum + copy h into F slot0
__global__ void k_prepA(const float* __restrict__ h) {
    int i = blockIdx.x * blockDim.x + threadIdx.x;
    if (i < NN * 16) {
        int r = i >> 4, p = i & 15;
        ((float4*)d_F)[(size_t)r * 64 + p] = ((const float4*)h)[i];
    }
    if (i < NN) { d_cnt[i] = 0; d_cur[i] = 0; }
    if (i < NG * D) d_gsum[i] = 0.f;
}

// prepB (persistent): count -> scan(off,dn) -> CSR fill
__global__ void __launch_bounds__(256, 4) k_prepB(const int* __restrict__ src,
                                                  const int* __restrict__ dst) {
    __shared__ int sh[256];
    int tid = threadIdx.x, b = blockIdx.x;
    int gt = b * 256 + tid;
    const int GS = PB * 256;

    for (int e = gt; e < EE; e += GS) atomicAdd(&d_cnt[dst[e]], 1);
    gbar(PB);

    {   // per-block chunk sums
        int i0 = b * CH;
        int v = 0;
        if (tid < CH && i0 + tid < NN) v = d_cnt[i0 + tid];
        sh[tid] = v;
        __syncthreads();
        for (int st = 128; st > 0; st >>= 1) {
            if (tid < st) sh[tid] += sh[tid + st];
            __syncthreads();
        }
        if (tid == 0) d_bsum[b] = sh[0];
    }
    gbar(PB);

    {   // exclusive prefix + deg_norm
        int part = 0;
        for (int i = tid; i < b; i += 256) part += d_bsum[i];
        sh[tid] = part;
        __syncthreads();
        for (int st = 128; st > 0; st >>= 1) {
            if (tid < st) sh[tid] += sh[tid + st];
            __syncthreads();
        }
        int base = sh[0];
        __syncthreads();

        int i0 = b * CH, idx = i0 + tid;
        int v = (tid < CH && idx < NN) ? d_cnt[idx] : 0;
        sh[tid] = v;
        __syncthreads();
        for (int st = 1; st < 256; st <<= 1) {
            int a = (tid >= st) ? sh[tid - st] : 0;
            __syncthreads();
            sh[tid] += a;
            __syncthreads();
        }
        if (tid < CH && idx < NN) {
            d_off[idx] = base + sh[tid] - v;
            d_dn[idx] = rsqrtf(fmaxf((float)v, 1.0f));
        }
        if (gt == 0) d_off[NN] = EE;
    }
    gbar(PB);

    for (int e = gt; e < EE; e += GS) {
        int dd = dst[e];
        int p = atomicAdd(&d_cur[dd], 1);
        d_csr[d_off[dd] + p] = src[e];
    }
}

// ---------------------------------------------------------------------------
// Hop (measured 29.7us): half-warp (16 lanes x float4) per node, prefetch-1.
__global__ void __launch_bounds__(256) k_hop(int hop) {
    int node = blockIdx.x * 16 + (threadIdx.x >> 4);    // grid 6250*16 == NN
    int lane = threadIdx.x & 15;
    int e0 = __ldg(d_off + node);
    int e1 = __ldg(d_off + node + 1);
    const float4* F4 = (const float4*)d_F;
    int slot_in = (hop - 1) * 16 + lane;
    float4 acc = make_float4(0.f, 0.f, 0.f, 0.f);
    int s = 0; float w = 0.f;
    if (e0 < e1) { s = __ldg(d_csr + e0); w = __ldg(d_dn + s); }
    for (int e = e0; e < e1; e++) {
        int sn = 0; float wn = 0.f;
        if (e + 1 < e1) { sn = __ldg(d_csr + e + 1); wn = __ldg(d_dn + sn); }
        float4 v = __ldg(F4 + (size_t)s * 64 + slot_in);
        acc.x = fmaf(v.x, w, acc.x);
        acc.y = fmaf(v.y, w, acc.y);
        acc.z = fmaf(v.z, w, acc.z);
        acc.w = fmaf(v.w, w, acc.w);
        s = sn; w = wn;
    }
    float dn = __ldg(d_dn + node);
    acc.x *= dn; acc.y *= dn; acc.z *= dn; acc.w *= dn;
    ((float4*)d_F)[(size_t)node * 64 + hop * 16 + lane] = acc;
}

// ---------------------------------------------------------------------------
// GEMM v4: f32x2 along K. Warp = 8 nodes x 64 cols; lane owns cols {lane, lane+32}.
// acc holds (even-k, odd-k) partial sums; horizontal add at the end.
// a-operand = ulonglong2 view of X float4 (free packing), b from conflict-free
// LDS.128 of permuted Wt. Per k-quad per lane: 8 uniform LDG + 2 LDS, 32 FFMA2.
__global__ void __launch_bounds__(128) k_gemm(int layer, const float* __restrict__ b) {
    __shared__ float Ws[8192];          // 32KB: 32 kq x (64c x 4k)
    int tid = threadIdx.x;
    int lane = tid & 31, warp = tid >> 5;
    int n0 = blockIdx.x * 32 + warp * 8;        // grid 3125 * 32 == NN exactly
    const float* Wt = d_Wt + layer * 16384;

    const ulonglong2* x0 = (const ulonglong2*)(d_F + (size_t)n0 * CD);  // row stride 64

    unsigned long long acc0[8], acc1[8];
#pragma unroll
    for (int n = 0; n < 8; n++) { acc0[n] = 0ull; acc1[n] = 0ull; }

    for (int ch = 0; ch < 2; ch++) {
        __syncthreads();
        for (int i = tid; i < 2048; i += 128)
            ((float4*)Ws)[i] = __ldg((const float4*)Wt + ch * 2048 + i);
        __syncthreads();
        const ulonglong2* Ws2 = (const ulonglong2*)Ws;

#pragma unroll 2
        for (int kq = 0; kq < 32; kq++) {
            int kgl = ch * 32 + kq;
            ulonglong2 bv0 = Ws2[kq * 64 + lane];        // cols lane
            ulonglong2 bv1 = Ws2[kq * 64 + 32 + lane];   // col lane+32
#pragma unroll
            for (int n = 0; n < 8; n++) {
                ulonglong2 a = __ldg(x0 + n * 64 + kgl); // X[n0+n][4k..4k+3] as 2 pairs
                ffma2(acc0[n], a.x, bv0.x);
                ffma2(acc1[n], a.x, bv1.x);
                ffma2(acc0[n], a.y, bv0.y);
                ffma2(acc1[n], a.y, bv1.y);
            }
        }
    }

    float bias0 = __ldg(b + lane);
    float bias1 = __ldg(b + 32 + lane);
    __syncwarp();   // all X reads in this warp done before in-place slot0 writes

#pragma unroll
    for (int n = 0; n < 8; n++) {
        float l0, h0, l1, h1;
        upk2(acc0[n], l0, h0);
        upk2(acc1[n], l1, h1);
        float o0 = fmaxf(l0 + h0 + bias0, 0.f);
        float o1 = fmaxf(l1 + h1 + bias1, 0.f);
        float* row = d_F + (size_t)(n0 + n) * CD;
        row[lane] = o0;
        row[32 + lane] = o1;
    }
}

// ---------------------------------------------------------------------------
// Per-graph sums of F slot0 (graph_ids sorted -> running-accumulator flush)
__global__ void k_gsum(const int* __restrict__ gid) {
    const int CHN = 512;
    int c = threadIdx.x & 63;
    int r0 = threadIdx.x >> 6;
    int nbeg = blockIdx.x * CHN + r0;
    int nend = min(NN, blockIdx.x * CHN + CHN);
    float acc = 0.f;
    int cur = -1;
    for (int n = nbeg; n < nend; n += 4) {
        int g = gid[n];
        if (g != cur) {
            if (cur >= 0) atomicAdd(&d_gsum[cur * D + c], acc);
            cur = g; acc = 0.f;
        }
        acc += d_F[(size_t)n * CD + c];
    }
    if (cur >= 0) atomicAdd(&d_gsum[cur * D + c], acc);
}

// Readout: mean -> @embW + embb -> L2 normalize.
__global__ void k_final(const int* __restrict__ gid,
                        const float* __restrict__ embW,
                        const float* __restrict__ embb,
                        float* __restrict__ out) {
    __shared__ float hg[NG][D];
    __shared__ int bnd[NG + 1];
    __shared__ float nrm[NG];
    int tid = threadIdx.x;

    if (tid <= NG) {
        int lo = 0, hi = NN;
        while (lo < hi) {
            int mid = (lo + hi) >> 1;
            if (gid[mid] < tid) lo = mid + 1; else hi = mid;
        }
        bnd[tid] = lo;
    }
    if (tid < NG) nrm[tid] = 0.f;
    __syncthreads();

    for (int idx = tid; idx < NG * D; idx += 128) {
        int g = idx >> 6;
        float cnt = (float)max(bnd[g + 1] - bnd[g], 1);
        hg[g][idx & 63] = d_gsum[idx] / cnt;
    }
    __syncthreads();

    for (int idx = tid; idx < NG * EMBD; idx += 128) {
        int g = idx >> 7, e = idx & 127;
        float s = embb[e];
#pragma unroll 16
        for (int k = 0; k < D; k++) s += hg[g][k] * embW[k * EMBD + e];
        atomicAdd(&nrm[g], s * s);
    }
    __syncthreads();

    for (int idx = tid; idx < NG * EMBD; idx += 128) {
        int g = idx >> 7, e = idx & 127;
        float s = embb[e];
#pragma unroll 16
        for (int k = 0; k < D; k++) s += hg[g][k] * embW[k * EMBD + e];
        float nv = fmaxf(sqrtf(nrm[g]), 1e-12f);
        out[idx] = s / nv;
    }
}

// ---------------------------------------------------------------------------
extern "C" void kernel_launch(void* const* d_in, const int* in_sizes, int n_in,
                              void* d_out, int out_size) {
    const float* h    = (const float*)d_in[0];
    const int*   src  = (const int*)d_in[1];
    const int*   dst  = (const int*)d_in[2];
    const int*   gid  = (const int*)d_in[3];
    const float* Wl[3] = {(const float*)d_in[4], (const float*)d_in[6], (const float*)d_in[8]};
    const float* bl[3] = {(const float*)d_in[5], (const float*)d_in[7], (const float*)d_in[9]};
    const float* embW = (const float*)d_in[10];
    const float* embb = (const float*)d_in[11];
    float* out = (float*)d_out;
    (void)in_sizes; (void)n_in; (void)out_size;

    k_prepWt<<<(3 * 16384 + 255) / 256, 256>>>(Wl[0], Wl[1], Wl[2]);  // 1
    k_prepA<<<(NN * 16 + 255) / 256, 256>>>(h);                       // 2
    k_prepB<<<PB, 256>>>(src, dst);                                   // 3

    for (int L = 0; L < 3; L++) {
        k_hop<<<NN / 16, 256>>>(1);                                   // 4 (L=0) <- profiled
        k_hop<<<NN / 16, 256>>>(2);
        k_hop<<<NN / 16, 256>>>(3);
        k_gemm<<<NN / 32, 128>>>(L, bl[L]);
    }

    k_gsum<<<(NN + 511) / 512, 256>>>(gid);
    k_final<<<1, 128>>>(gid, embW, embb, out);
}

// round 8
// speedup vs baseline: 1.8971x; 1.4965x over previous
#include <cuda_runtime.h>

#define NN   100000
#define EE   800000
#define D    64
#define CD   256          // (HOPS+1)*D
#define NG   64
#define EMBD 128
#define PB   512          // prepB persistent blocks ((256,4): 592 slots >= 512)
#define CH   196          // nodes per prepB chunk (512*196 >= NN)
#define HB   888          // hops3 blocks ((256,6): 148*6 = 888 exactly)

// Persistent scratch
__device__ float d_F[(size_t)NN * CD];   // concat features [N][256]
__device__ float d_Wt[3 * 16384];        // permuted weights [L][kq][c][4k]
__device__ int   d_cnt[NN];
__device__ int   d_cur[NN];
__device__ int   d_off[NN + 1];
__device__ int   d_csr[EE];
__device__ int   d_bsum[PB];
__device__ float d_dn[NN];
__device__ float d_gsum[NG * D];
__device__ int   d_bar_cnt = 0;
__device__ int   d_bar_gen = 0;

// ---------------------------------------------------------------------------
__device__ __forceinline__ void upk2(unsigned long long v, float& lo, float& hi) {
    asm("mov.b64 {%0,%1}, %2;" : "=f"(lo), "=f"(hi) : "l"(v));
}
__device__ __forceinline__ void ffma2(unsigned long long& d, unsigned long long a,
                                      unsigned long long b) {
    asm("fma.rn.f32x2 %0, %1, %2, %0;" : "+l"(d) : "l"(a), "l"(b));
}

// Software grid barrier; all nblk blocks co-resident.
__device__ __forceinline__ void gbar(int nblk) {
    __threadfence();
    __syncthreads();
    if (threadIdx.x == 0) {
        int g = *((volatile int*)&d_bar_gen);
        int r = atomicAdd(&d_bar_cnt, 1);
        if (r == nblk - 1) {
            d_bar_cnt = 0;
            __threadfence();
            atomicAdd(&d_bar_gen, 1);
        } else {
            while (*((volatile int*)&d_bar_gen) == g) {}
        }
    }
    __syncthreads();
}

// ---------------------------------------------------------------------------
// prep0: copy h into F slot0, zero counters/gsum, permute W -> Wt [kq][c][4k]
__global__ void k_prep0(const float* __restrict__ h, const float* __restrict__ W0,
                        const float* __restrict__ W1, const float* __restrict__ W2) {
    int i = blockIdx.x * blockDim.x + threadIdx.x;
    if (i < NN * 16) {
        int r = i >> 4, p = i & 15;
        ((float4*)d_F)[(size_t)r * 64 + p] = ((const float4*)h)[i];
    }
    if (i < NN) { d_cnt[i] = 0; d_cur[i] = 0; }
    if (i < NG * D) d_gsum[i] = 0.f;
    if (i < 3 * 16384) {
        int L = i / 16384, gi = i - L * 16384;
        int kq = gi >> 8, r = gi & 255;
        int c = r >> 2, kk = r & 3;
        const float* W = (L == 0) ? W0 : (L == 1) ? W1 : W2;
        d_Wt[i] = W[(kq * 4 + kk) * 64 + c];
    }
}

// prepB (persistent): count -> scan(off,dn) -> CSR fill
__global__ void __launch_bounds__(256, 4) k_prepB(const int* __restrict__ src,
                                                  const int* __restrict__ dst) {
    __shared__ int sh[256];
    int tid = threadIdx.x, b = blockIdx.x;
    int gt = b * 256 + tid;
    const int GS = PB * 256;

    for (int e = gt; e < EE; e += GS) atomicAdd(&d_cnt[dst[e]], 1);
    gbar(PB);

    {   // per-block chunk sums
        int i0 = b * CH;
        int v = 0;
        if (tid < CH && i0 + tid < NN) v = d_cnt[i0 + tid];
        sh[tid] = v;
        __syncthreads();
        for (int st = 128; st > 0; st >>= 1) {
            if (tid < st) sh[tid] += sh[tid + st];
            __syncthreads();
        }
        if (tid == 0) d_bsum[b] = sh[0];
    }
    gbar(PB);

    {   // exclusive prefix + deg_norm
        int part = 0;
        for (int i = tid; i < b; i += 256) part += d_bsum[i];
        sh[tid] = part;
        __syncthreads();
        for (int st = 128; st > 0; st >>= 1) {
            if (tid < st) sh[tid] += sh[tid + st];
            __syncthreads();
        }
        int base = sh[0];
        __syncthreads();

        int i0 = b * CH, idx = i0 + tid;
        int v = (tid < CH && idx < NN) ? d_cnt[idx] : 0;
        sh[tid] = v;
        __syncthreads();
        for (int st = 1; st < 256; st <<= 1) {
            int a = (tid >= st) ? sh[tid - st] : 0;
            __syncthreads();
            sh[tid] += a;
            __syncthreads();
        }
        if (tid < CH && idx < NN) {
            d_off[idx] = base + sh[tid] - v;
            d_dn[idx] = rsqrtf(fmaxf((float)v, 1.0f));
        }
        if (gt == 0) d_off[NN] = EE;
    }
    gbar(PB);

    for (int e = gt; e < EE; e += GS) {
        int dd = dst[e];
        int p = atomicAdd(&d_cur[dd], 1);
        d_csr[d_off[dd] + p] = src[e];
    }
}

// ---------------------------------------------------------------------------
// hops3 (persistent, 888 co-resident blocks): 3 hops with grid barriers.
// Inner loop = the measured-good prefetch-1 half-warp gather (32 regs).
__global__ void __launch_bounds__(256, 6) k_hops3() {
    int grp = threadIdx.x >> 4;
    int lane = threadIdx.x & 15;
    const float4* F4 = (const float4*)d_F;

    for (int hop = 1; hop <= 3; hop++) {
        int slot_in = (hop - 1) * 16 + lane;
        for (int node = blockIdx.x * 16 + grp; node < NN; node += HB * 16) {
            int e0 = __ldg(d_off + node);
            int e1 = __ldg(d_off + node + 1);
            float4 acc = make_float4(0.f, 0.f, 0.f, 0.f);
            int s = 0; float w = 0.f;
            if (e0 < e1) { s = __ldg(d_csr + e0); w = __ldg(d_dn + s); }
            for (int e = e0; e < e1; e++) {
                int sn = 0; float wn = 0.f;
                if (e + 1 < e1) { sn = __ldg(d_csr + e + 1); wn = __ldg(d_dn + sn); }
                float4 v = __ldg(F4 + (size_t)s * 64 + slot_in);
                acc.x = fmaf(v.x, w, acc.x);
                acc.y = fmaf(v.y, w, acc.y);
                acc.z = fmaf(v.z, w, acc.z);
                acc.w = fmaf(v.w, w, acc.w);
                s = sn; w = wn;
            }
            float dn = __ldg(d_dn + node);
            acc.x *= dn; acc.y *= dn; acc.z *= dn; acc.w *= dn;
            ((float4*)d_F)[(size_t)node * 64 + hop * 16 + lane] = acc;
        }
        if (hop < 3) gbar(HB);
    }
}

// ---------------------------------------------------------------------------
// GEMM v5: block = 64 nodes x 64 cols; K in 4 chunks of 64. X AND W staged in
// smem (padded, conflict-free). Lane = 2 nodes x 8 consecutive cols.
// Per k-quad per lane: 2 LDS(X) + 8 LDS(W) + 32 FFMA2 -> FFMA2-bound.
__global__ void __launch_bounds__(256) k_gemm(int layer, const float* __restrict__ b) {
    __shared__ float Xs[64 * 68];       // [node][68] (4-float pad)
    __shared__ float Wsm[16 * 288];     // [kq][c*4 + (c>>3)*4] (16B pad per 128B)
    int tid = threadIdx.x;
    int lane = tid & 31, warp = tid >> 5;
    int ng = lane & 3, cg = lane >> 2;
    int n0 = blockIdx.x * 64;
    int na = warp * 8 + ng * 2;          // lane's node pair within block: na, na+1
    const float4* Wt4 = (const float4*)(d_Wt + layer * 16384);
    const float4* F4 = (const float4*)d_F;

    unsigned long long acc[2][8];
#pragma unroll
    for (int j = 0; j < 2; j++)
#pragma unroll
        for (int i = 0; i < 8; i++) acc[j][i] = 0ull;

    for (int ch = 0; ch < 4; ch++) {
        __syncthreads();
        // cooperative X tile load: 64 nodes x 16 float4
#pragma unroll
        for (int t = 0; t < 4; t++) {
            int i = tid + t * 256;
            int n = i >> 4, f = i & 15;
            float4 v = make_float4(0.f, 0.f, 0.f, 0.f);
            if (n0 + n < NN) v = __ldg(F4 + (size_t)(n0 + n) * 64 + ch * 16 + f);
            *(float4*)(Xs + n * 68 + f * 4) = v;
        }
        // cooperative W chunk load: 16 kq x 64 c  (padded store)
#pragma unroll
        for (int t = 0; t < 4; t++) {
            int i = tid + t * 256;
            int kq = i >> 6, c = i & 63;
            float4 v = __ldg(Wt4 + ch * 1024 + i);
            *(float4*)(Wsm + kq * 288 + c * 4 + (c >> 3) * 4) = v;
        }
        __syncthreads();

#pragma unroll 4
        for (int kq = 0; kq < 16; kq++) {
            ulonglong2 xa = *(const ulonglong2*)(Xs + (na + 0) * 68 + kq * 4);
            ulonglong2 xb = *(const ulonglong2*)(Xs + (na + 1) * 68 + kq * 4);
            const float* wrow = Wsm + kq * 288 + cg * 36;
#pragma unroll
            for (int i = 0; i < 8; i++) {
                ulonglong2 w = *(const ulonglong2*)(wrow + i * 4);
                ffma2(acc[0][i], xa.x, w.x);
                ffma2(acc[0][i], xa.y, w.y);
                ffma2(acc[1][i], xb.x, w.x);
                ffma2(acc[1][i], xb.y, w.y);
            }
        }
    }

    // epilogue: lane writes 2 nodes x cols [cg*8, cg*8+8) as 2 float4 each
    float4 bv0 = __ldg((const float4*)b + cg * 2);
    float4 bv1 = __ldg((const float4*)b + cg * 2 + 1);
    float bias[8] = {bv0.x, bv0.y, bv0.z, bv0.w, bv1.x, bv1.y, bv1.z, bv1.w};
#pragma unroll
    for (int j = 0; j < 2; j++) {
        int n = n0 + na + j;
        if (n >= NN) continue;
        float o[8];
#pragma unroll
        for (int i = 0; i < 8; i++) {
            float lo, hi;
            upk2(acc[j][i], lo, hi);
            o[i] = fmaxf(lo + hi + bias[i], 0.f);
        }
        float* row = d_F + (size_t)n * CD + cg * 8;
        *(float4*)row = make_float4(o[0], o[1], o[2], o[3]);
        *(float4*)(row + 4) = make_float4(o[4], o[5], o[6], o[7]);
    }
}

// ---------------------------------------------------------------------------
// Per-graph sums of F slot0 (graph_ids sorted -> running-accumulator flush)
__global__ void k_gsum(const int* __restrict__ gid) {
    const int CHN = 512;
    int c = threadIdx.x & 63;
    int r0 = threadIdx.x >> 6;
    int nbeg = blockIdx.x * CHN + r0;
    int nend = min(NN, blockIdx.x * CHN + CHN);
    float acc = 0.f;
    int cur = -1;
    for (int n = nbeg; n < nend; n += 4) {
        int g = gid[n];
        if (g != cur) {
            if (cur >= 0) atomicAdd(&d_gsum[cur * D + c], acc);
            cur = g; acc = 0.f;
        }
        acc += d_F[(size_t)n * CD + c];
    }
    if (cur >= 0) atomicAdd(&d_gsum[cur * D + c], acc);
}

// Readout: mean -> @embW + embb -> L2 normalize. One block, 256 threads.
__global__ void k_final(const int* __restrict__ gid,
                        const float* __restrict__ embW,
                        const float* __restrict__ embb,
                        float* __restrict__ out) {
    __shared__ float hg[NG][D];
    __shared__ int bnd[NG + 1];
    __shared__ float nrm[NG];
    int tid = threadIdx.x;

    if (tid <= NG) {
        int lo = 0, hi = NN;
        while (lo < hi) {
            int mid = (lo + hi) >> 1;
            if (gid[mid] < tid) lo = mid + 1; else hi = mid;
        }
        bnd[tid] = lo;
    }
    if (tid < NG) nrm[tid] = 0.f;
    __syncthreads();

    for (int idx = tid; idx < NG * D; idx += 256) {
        int g = idx >> 6;
        float cnt = (float)max(bnd[g + 1] - bnd[g], 1);
        hg[g][idx & 63] = d_gsum[idx] / cnt;
    }
    __syncthreads();

    for (int idx = tid; idx < NG * EMBD; idx += 256) {
        int g = idx >> 7, e = idx & 127;
        float s = embb[e];
#pragma unroll 16
        for (int k = 0; k < D; k++) s += hg[g][k] * embW[k * EMBD + e];
        atomicAdd(&nrm[g], s * s);
    }
    __syncthreads();

    for (int idx = tid; idx < NG * EMBD; idx += 256) {
        int g = idx >> 7, e = idx & 127;
        float s = embb[e];
#pragma unroll 16
        for (int k = 0; k < D; k++) s += hg[g][k] * embW[k * EMBD + e];
        float nv = fmaxf(sqrtf(nrm[g]), 1e-12f);
        out[idx] = s / nv;
    }
}

// ---------------------------------------------------------------------------
extern "C" void kernel_launch(void* const* d_in, const int* in_sizes, int n_in,
                              void* d_out, int out_size) {
    const float* h    = (const float*)d_in[0];
    const int*   src  = (const int*)d_in[1];
    const int*   dst  = (const int*)d_in[2];
    const int*   gid  = (const int*)d_in[3];
    const float* Wl[3] = {(const float*)d_in[4], (const float*)d_in[6], (const float*)d_in[8]};
    const float* bl[3] = {(const float*)d_in[5], (const float*)d_in[7], (const float*)d_in[9]};
    const float* embW = (const float*)d_in[10];
    const float* embb = (const float*)d_in[11];
    float* out = (float*)d_out;
    (void)in_sizes; (void)n_in; (void)out_size;

    k_prep0<<<(NN * 16 + 255) / 256, 256>>>(h, Wl[0], Wl[1], Wl[2]);  // 1
    k_prepB<<<PB, 256>>>(src, dst);                                   // 2

    for (int L = 0; L < 3; L++) {
        k_hops3<<<HB, 256>>>();                                       // 3 (L=0)
        k_gemm<<<(NN + 63) / 64, 256>>>(L, bl[L]);                    // 4 (L=0) <- profiled
    }

    k_gsum<<<(NN + 511) / 512, 256>>>(gid);
    k_final<<<1, 256>>>(gid, embW, embb, out);
}

// round 9
// speedup vs baseline: 1.9087x; 1.0061x over previous
#include <cuda_runtime.h>

#define NN   100000
#define EE   800000
#define D    64
#define CD   256          // (HOPS+1)*D
#define NG   64
#define EMBD 128
#define PB   512          // prepB persistent blocks ((256,4): >= 512 slots)
#define CH   196          // nodes per prepB chunk (512*196 >= NN)
#define HB   888          // hops3 blocks ((256,6): 148*6 = 888 exactly)

// Persistent scratch
__device__ float d_F[(size_t)NN * CD];   // concat features [N][256]
__device__ float d_Wt[3 * 16384];        // permuted weights [L][kq][c][4k]
__device__ int   d_cnt[NN];
__device__ int   d_cur[NN];
__device__ int   d_off[NN + 1];
__device__ int   d_csr[EE];
__device__ int   d_bsum[PB];
__device__ float d_dn[NN];
__device__ float d_gsum[NG * D];
__device__ int   d_bar_cnt = 0;
__device__ int   d_bar_gen = 0;

// ---------------------------------------------------------------------------
__device__ __forceinline__ void upk2(unsigned long long v, float& lo, float& hi) {
    asm("mov.b64 {%0,%1}, %2;" : "=f"(lo), "=f"(hi) : "l"(v));
}
__device__ __forceinline__ void ffma2(unsigned long long& d, unsigned long long a,
                                      unsigned long long b) {
    asm("fma.rn.f32x2 %0, %1, %2, %0;" : "+l"(d) : "l"(a), "l"(b));
}

// Software grid barrier; all nblk blocks co-resident.
__device__ __forceinline__ void gbar(int nblk) {
    __threadfence();
    __syncthreads();
    if (threadIdx.x == 0) {
        int g = *((volatile int*)&d_bar_gen);
        int r = atomicAdd(&d_bar_cnt, 1);
        if (r == nblk - 1) {
            d_bar_cnt = 0;
            __threadfence();
            atomicAdd(&d_bar_gen, 1);
        } else {
            while (*((volatile int*)&d_bar_gen) == g) {}
        }
    }
    __syncthreads();
}

// ---------------------------------------------------------------------------
// prep0: copy h into F slot0, zero counters/gsum, permute W -> Wt [kq][c][4k]
__global__ void k_prep0(const float* __restrict__ h, const float* __restrict__ W0,
                        const float* __restrict__ W1, const float* __restrict__ W2) {
    int i = blockIdx.x * blockDim.x + threadIdx.x;
    if (i < NN * 16) {
        int r = i >> 4, p = i & 15;
        ((float4*)d_F)[(size_t)r * 64 + p] = ((const float4*)h)[i];
    }
    if (i < NN) { d_cnt[i] = 0; d_cur[i] = 0; }
    if (i < NG * D) d_gsum[i] = 0.f;
    if (i < 3 * 16384) {
        int L = i / 16384, gi = i - L * 16384;
        int kq = gi >> 8, r = gi & 255;
        int c = r >> 2, kk = r & 3;
        const float* W = (L == 0) ? W0 : (L == 1) ? W1 : W2;
        d_Wt[i] = W[(kq * 4 + kk) * 64 + c];
    }
}

// prepB (persistent): count -> scan(off,dn) -> CSR fill
__global__ void __launch_bounds__(256, 4) k_prepB(const int* __restrict__ src,
                                                  const int* __restrict__ dst) {
    __shared__ int sh[256];
    int tid = threadIdx.x, b = blockIdx.x;
    int gt = b * 256 + tid;
    const int GS = PB * 256;

    for (int e = gt; e < EE; e += GS) atomicAdd(&d_cnt[dst[e]], 1);
    gbar(PB);

    {   // per-block chunk sums
        int i0 = b * CH;
        int v = 0;
        if (tid < CH && i0 + tid < NN) v = d_cnt[i0 + tid];
        sh[tid] = v;
        __syncthreads();
        for (int st = 128; st > 0; st >>= 1) {
            if (tid < st) sh[tid] += sh[tid + st];
            __syncthreads();
        }
        if (tid == 0) d_bsum[b] = sh[0];
    }
    gbar(PB);

    {   // exclusive prefix + deg_norm
        int part = 0;
        for (int i = tid; i < b; i += 256) part += d_bsum[i];
        sh[tid] = part;
        __syncthreads();
        for (int st = 128; st > 0; st >>= 1) {
            if (tid < st) sh[tid] += sh[tid + st];
            __syncthreads();
        }
        int base = sh[0];
        __syncthreads();

        int i0 = b * CH, idx = i0 + tid;
        int v = (tid < CH && idx < NN) ? d_cnt[idx] : 0;
        sh[tid] = v;
        __syncthreads();
        for (int st = 1; st < 256; st <<= 1) {
            int a = (tid >= st) ? sh[tid - st] : 0;
            __syncthreads();
            sh[tid] += a;
            __syncthreads();
        }
        if (tid < CH && idx < NN) {
            d_off[idx] = base + sh[tid] - v;
            d_dn[idx] = rsqrtf(fmaxf((float)v, 1.0f));
        }
        if (gt == 0) d_off[NN] = EE;
    }
    gbar(PB);

    for (int e = gt; e < EE; e += GS) {
        int dd = dst[e];
        int p = atomicAdd(&d_cur[dd], 1);
        d_csr[d_off[dd] + p] = src[e];
    }
}

// ---------------------------------------------------------------------------
// hops3 (persistent, 888 co-resident blocks): 3 hops with grid barriers.
// Inner loop = the measured-good prefetch-1 half-warp gather (32 regs).
__global__ void __launch_bounds__(256, 6) k_hops3() {
    int grp = threadIdx.x >> 4;
    int lane = threadIdx.x & 15;
    const float4* F4 = (const float4*)d_F;

    for (int hop = 1; hop <= 3; hop++) {
        int slot_in = (hop - 1) * 16 + lane;
        for (int node = blockIdx.x * 16 + grp; node < NN; node += HB * 16) {
            int e0 = __ldg(d_off + node);
            int e1 = __ldg(d_off + node + 1);
            float4 acc = make_float4(0.f, 0.f, 0.f, 0.f);
            int s = 0; float w = 0.f;
            if (e0 < e1) { s = __ldg(d_csr + e0); w = __ldg(d_dn + s); }
            for (int e = e0; e < e1; e++) {
                int sn = 0; float wn = 0.f;
                if (e + 1 < e1) { sn = __ldg(d_csr + e + 1); wn = __ldg(d_dn + sn); }
                float4 v = __ldg(F4 + (size_t)s * 64 + slot_in);
                acc.x = fmaf(v.x, w, acc.x);
                acc.y = fmaf(v.y, w, acc.y);
                acc.z = fmaf(v.z, w, acc.z);
                acc.w = fmaf(v.w, w, acc.w);
                s = sn; w = wn;
            }
            float dn = __ldg(d_dn + node);
            acc.x *= dn; acc.y *= dn; acc.z *= dn; acc.w *= dn;
            ((float4*)d_F)[(size_t)node * 64 + hop * 16 + lane] = acc;
        }
        if (hop < 3) gbar(HB);
    }
}

// ---------------------------------------------------------------------------
// GEMM v6: block = 64 nodes; warp = 8 nodes x 64 cols; lane owns cols
// {lane, lane+32}. X reads are BROADCAST (uniform address -> crossbar N=1);
// W reads are 512B-contiguous conflict-free LDS.128.
// Crossbar/warp/kq = 1152B (36 cyc/SM for 4 warps) < 64 FFMA2 cyc -> FFMA2-bound.
__global__ void __launch_bounds__(256) k_gemm(int layer, const float* __restrict__ b) {
    __shared__ float Xs[64 * 64];        // 16KB: [node][64 floats of K chunk]
    __shared__ float Wsm[16 * 256];      // 16KB: [kq][c][4k]
    int tid = threadIdx.x;
    int lane = tid & 31, warp = tid >> 5;
    int n0 = blockIdx.x * 64;
    int nb = warp * 8;                   // warp's 8 nodes within the block
    const float4* Wt4 = (const float4*)(d_Wt + layer * 16384);
    const float4* F4 = (const float4*)d_F;

    unsigned long long acc0[8], acc1[8];
#pragma unroll
    for (int n = 0; n < 8; n++) { acc0[n] = 0ull; acc1[n] = 0ull; }

    for (int ch = 0; ch < 4; ch++) {
        __syncthreads();
        // X tile: 64 nodes x 16 float4 (coalesced, conflict-free)
#pragma unroll
        for (int t = 0; t < 4; t++) {
            int i = tid + t * 256;
            int n = i >> 4, f = i & 15;
            float4 v = make_float4(0.f, 0.f, 0.f, 0.f);
            if (n0 + n < NN) v = __ldg(F4 + (size_t)(n0 + n) * 64 + ch * 16 + f);
            *(float4*)(Xs + n * 64 + f * 4) = v;
        }
        // W chunk: 16 kq x 256 floats
#pragma unroll
        for (int t = 0; t < 4; t++) {
            int i = tid + t * 256;
            ((float4*)Wsm)[i] = __ldg(Wt4 + ch * 1024 + i);
        }
        __syncthreads();
        const ulonglong2* Ws2 = (const ulonglong2*)Wsm;

#pragma unroll 4
        for (int kq = 0; kq < 16; kq++) {
            ulonglong2 w0 = Ws2[kq * 64 + lane];         // col lane   (conflict-free)
            ulonglong2 w1 = Ws2[kq * 64 + 32 + lane];    // col lane+32
#pragma unroll
            for (int n = 0; n < 8; n++) {
                ulonglong2 x = *(const ulonglong2*)(Xs + (nb + n) * 64 + kq * 4); // broadcast
                ffma2(acc0[n], x.x, w0.x);
                ffma2(acc0[n], x.y, w0.y);
                ffma2(acc1[n], x.x, w1.x);
                ffma2(acc1[n], x.y, w1.y);
            }
        }
    }

    // epilogue: lane writes cols {lane, lane+32} of its warp's 8 nodes.
    // All F reads happened in the staging phases (before syncs), so in-place
    // slot0 writes are safe.
    float bias0 = __ldg(b + lane);
    float bias1 = __ldg(b + 32 + lane);
#pragma unroll
    for (int n = 0; n < 8; n++) {
        int node = n0 + nb + n;
        if (node < NN) {
            float l0, h0, l1, h1;
            upk2(acc0[n], l0, h0);
            upk2(acc1[n], l1, h1);
            float* row = d_F + (size_t)node * CD;
            row[lane]      = fmaxf(l0 + h0 + bias0, 0.f);
            row[32 + lane] = fmaxf(l1 + h1 + bias1, 0.f);
        }
    }
}

// ---------------------------------------------------------------------------
// Per-graph sums of F slot0 (graph_ids sorted -> running-accumulator flush)
__global__ void k_gsum(const int* __restrict__ gid) {
    const int CHN = 512;
    int c = threadIdx.x & 63;
    int r0 = threadIdx.x >> 6;
    int nbeg = blockIdx.x * CHN + r0;
    int nend = min(NN, blockIdx.x * CHN + CHN);
    float acc = 0.f;
    int cur = -1;
    for (int n = nbeg; n < nend; n += 4) {
        int g = gid[n];
        if (g != cur) {
            if (cur >= 0) atomicAdd(&d_gsum[cur * D + c], acc);
            cur = g; acc = 0.f;
        }
        acc += d_F[(size_t)n * CD + c];
    }
    if (cur >= 0) atomicAdd(&d_gsum[cur * D + c], acc);
}

// Readout: mean -> @embW + embb -> L2 normalize. One block, 256 threads.
__global__ void k_final(const int* __restrict__ gid,
                        const float* __restrict__ embW,
                        const float* __restrict__ embb,
                        float* __restrict__ out) {
    __shared__ float hg[NG][D];
    __shared__ int bnd[NG + 1];
    __shared__ float nrm[NG];
    int tid = threadIdx.x;

    if (tid <= NG) {
        int lo = 0, hi = NN;
        while (lo < hi) {
            int mid = (lo + hi) >> 1;
            if (gid[mid] < tid) lo = mid + 1; else hi = mid;
        }
        bnd[tid] = lo;
    }
    if (tid < NG) nrm[tid] = 0.f;
    __syncthreads();

    for (int idx = tid; idx < NG * D; idx += 256) {
        int g = idx >> 6;
        float cnt = (float)max(bnd[g + 1] - bnd[g], 1);
        hg[g][idx & 63] = d_gsum[idx] / cnt;
    }
    __syncthreads();

    for (int idx = tid; idx < NG * EMBD; idx += 256) {
        int g = idx >> 7, e = idx & 127;
        float s = embb[e];
#pragma unroll 16
        for (int k = 0; k < D; k++) s += hg[g][k] * embW[k * EMBD + e];
        atomicAdd(&nrm[g], s * s);
    }
    __syncthreads();

    for (int idx = tid; idx < NG * EMBD; idx += 256) {
        int g = idx >> 7, e = idx & 127;
        float s = embb[e];
#pragma unroll 16
        for (int k = 0; k < D; k++) s += hg[g][k] * embW[k * EMBD + e];
        float nv = fmaxf(sqrtf(nrm[g]), 1e-12f);
        out[idx] = s / nv;
    }
}

// ---------------------------------------------------------------------------
extern "C" void kernel_launch(void* const* d_in, const int* in_sizes, int n_in,
                              void* d_out, int out_size) {
    const float* h    = (const float*)d_in[0];
    const int*   src  = (const int*)d_in[1];
    const int*   dst  = (const int*)d_in[2];
    const int*   gid  = (const int*)d_in[3];
    const float* Wl[3] = {(const float*)d_in[4], (const float*)d_in[6], (const float*)d_in[8]};
    const float* bl[3] = {(const float*)d_in[5], (const float*)d_in[7], (const float*)d_in[9]};
    const float* embW = (const float*)d_in[10];
    const float* embb = (const float*)d_in[11];
    float* out = (float*)d_out;
    (void)in_sizes; (void)n_in; (void)out_size;

    k_prep0<<<(NN * 16 + 255) / 256, 256>>>(h, Wl[0], Wl[1], Wl[2]);  // 1
    k_prepB<<<PB, 256>>>(src, dst);                                   // 2

    for (int L = 0; L < 3; L++) {
        k_hops3<<<HB, 256>>>();                                       // 3 (L=0)
        k_gemm<<<(NN + 63) / 64, 256>>>(L, bl[L]);                    // 4 (L=0) <- profiled
    }

    k_gsum<<<(NN + 511) / 512, 256>>>(gid);
    k_final<<<1, 256>>>(gid, embW, embb, out);
}

// round 10
// speedup vs baseline: 1.9434x; 1.0182x over previous
#include <cuda_runtime.h>

#define NN   100000
#define EE   800000
#define D    64
#define CD   256          // (HOPS+1)*D
#define NG   64
#define EMBD 128
#define PB   512          // prepB persistent blocks ((256,4): >= 512 slots)
#define CH   196          // nodes per prepB chunk (512*196 >= NN)
#define HB   888          // hops3 blocks ((256,6): 148*6 = 888 exactly)

// Persistent scratch
__device__ float d_F[(size_t)NN * CD];   // concat features [N][256]
__device__ float d_Wt[3 * 16384];        // permuted weights [L][kq][c][4k]
__device__ int   d_cnt[NN];
__device__ int   d_cur[NN];
__device__ int   d_off[NN + 1];
__device__ int   d_csr[EE];
__device__ int   d_bsum[PB];
__device__ float d_dn[NN];
__device__ float d_gsum[NG * D];
__device__ int   d_bar_cnt = 0;
__device__ int   d_bar_gen = 0;

// ---------------------------------------------------------------------------
__device__ __forceinline__ void upk2(unsigned long long v, float& lo, float& hi) {
    asm("mov.b64 {%0,%1}, %2;" : "=f"(lo), "=f"(hi) : "l"(v));
}
__device__ __forceinline__ void ffma2(unsigned long long& d, unsigned long long a,
                                      unsigned long long b) {
    asm("fma.rn.f32x2 %0, %1, %2, %0;" : "+l"(d) : "l"(a), "l"(b));
}
__device__ __forceinline__ void cpa16(unsigned int saddr, const void* gaddr) {
    asm volatile("cp.async.cg.shared.global [%0], [%1], 16;" :: "r"(saddr), "l"(gaddr));
}
__device__ __forceinline__ void cpa_commit() {
    asm volatile("cp.async.commit_group;");
}
template <int N> __device__ __forceinline__ void cpa_wait() {
    asm volatile("cp.async.wait_group %0;" :: "n"(N));
}

// Software grid barrier; all nblk blocks co-resident.
__device__ __forceinline__ void gbar(int nblk) {
    __threadfence();
    __syncthreads();
    if (threadIdx.x == 0) {
        int g = *((volatile int*)&d_bar_gen);
        int r = atomicAdd(&d_bar_cnt, 1);
        if (r == nblk - 1) {
            d_bar_cnt = 0;
            __threadfence();
            atomicAdd(&d_bar_gen, 1);
        } else {
            while (*((volatile int*)&d_bar_gen) == g) {}
        }
    }
    __syncthreads();
}

// ---------------------------------------------------------------------------
// prep0: copy h into F slot0, zero counters/gsum, permute W -> Wt [kq][c][4k]
__global__ void k_prep0(const float* __restrict__ h, const float* __restrict__ W0,
                        const float* __restrict__ W1, const float* __restrict__ W2) {
    int i = blockIdx.x * blockDim.x + threadIdx.x;
    if (i < NN * 16) {
        int r = i >> 4, p = i & 15;
        ((float4*)d_F)[(size_t)r * 64 + p] = ((const float4*)h)[i];
    }
    if (i < NN) { d_cnt[i] = 0; d_cur[i] = 0; }
    if (i < NG * D) d_gsum[i] = 0.f;
    if (i < 3 * 16384) {
        int L = i / 16384, gi = i - L * 16384;
        int kq = gi >> 8, r = gi & 255;
        int c = r >> 2, kk = r & 3;
        const float* W = (L == 0) ? W0 : (L == 1) ? W1 : W2;
        d_Wt[i] = W[(kq * 4 + kk) * 64 + c];
    }
}

// prepB (persistent): count -> scan(off,dn) -> CSR fill
__global__ void __launch_bounds__(256, 4) k_prepB(const int* __restrict__ src,
                                                  const int* __restrict__ dst) {
    __shared__ int sh[256];
    int tid = threadIdx.x, b = blockIdx.x;
    int gt = b * 256 + tid;
    const int GS = PB * 256;

    for (int e = gt; e < EE; e += GS) atomicAdd(&d_cnt[dst[e]], 1);
    gbar(PB);

    {   // per-block chunk sums
        int i0 = b * CH;
        int v = 0;
        if (tid < CH && i0 + tid < NN) v = d_cnt[i0 + tid];
        sh[tid] = v;
        __syncthreads();
        for (int st = 128; st > 0; st >>= 1) {
            if (tid < st) sh[tid] += sh[tid + st];
            __syncthreads();
        }
        if (tid == 0) d_bsum[b] = sh[0];
    }
    gbar(PB);

    {   // exclusive prefix + deg_norm
        int part = 0;
        for (int i = tid; i < b; i += 256) part += d_bsum[i];
        sh[tid] = part;
        __syncthreads();
        for (int st = 128; st > 0; st >>= 1) {
            if (tid < st) sh[tid] += sh[tid + st];
            __syncthreads();
        }
        int base = sh[0];
        __syncthreads();

        int i0 = b * CH, idx = i0 + tid;
        int v = (tid < CH && idx < NN) ? d_cnt[idx] : 0;
        sh[tid] = v;
        __syncthreads();
        for (int st = 1; st < 256; st <<= 1) {
            int a = (tid >= st) ? sh[tid - st] : 0;
            __syncthreads();
            sh[tid] += a;
            __syncthreads();
        }
        if (tid < CH && idx < NN) {
            d_off[idx] = base + sh[tid] - v;
            d_dn[idx] = rsqrtf(fmaxf((float)v, 1.0f));
        }
        if (gt == 0) d_off[NN] = EE;
    }
    gbar(PB);

    for (int e = gt; e < EE; e += GS) {
        int dd = dst[e];
        int p = atomicAdd(&d_cur[dd], 1);
        d_csr[d_off[dd] + p] = src[e];
    }
}

// ---------------------------------------------------------------------------
// hops3 (persistent, 888 co-resident blocks): 3 hops with grid barriers.
__global__ void __launch_bounds__(256, 6) k_hops3() {
    int grp = threadIdx.x >> 4;
    int lane = threadIdx.x & 15;
    const float4* F4 = (const float4*)d_F;

    for (int hop = 1; hop <= 3; hop++) {
        int slot_in = (hop - 1) * 16 + lane;
        for (int node = blockIdx.x * 16 + grp; node < NN; node += HB * 16) {
            int e0 = __ldg(d_off + node);
            int e1 = __ldg(d_off + node + 1);
            float4 acc = make_float4(0.f, 0.f, 0.f, 0.f);
            int s = 0; float w = 0.f;
            if (e0 < e1) { s = __ldg(d_csr + e0); w = __ldg(d_dn + s); }
            for (int e = e0; e < e1; e++) {
                int sn = 0; float wn = 0.f;
                if (e + 1 < e1) { sn = __ldg(d_csr + e + 1); wn = __ldg(d_dn + sn); }
                float4 v = __ldg(F4 + (size_t)s * 64 + slot_in);
                acc.x = fmaf(v.x, w, acc.x);
                acc.y = fmaf(v.y, w, acc.y);
                acc.z = fmaf(v.z, w, acc.z);
                acc.w = fmaf(v.w, w, acc.w);
                s = sn; w = wn;
            }
            float dn = __ldg(d_dn + node);
            acc.x *= dn; acc.y *= dn; acc.z *= dn; acc.w *= dn;
            ((float4*)d_F)[(size_t)node * 64 + hop * 16 + lane] = acc;
        }
        if (hop < 3) gbar(HB);
    }
}

// ---------------------------------------------------------------------------
// GEMM v7: block = 64 nodes; warp = 8 nodes x 64 cols; lane owns cols
// {lane, lane+32}. K chunked x8 (32 k); X and W double-buffered via cp.async
// so staging overlaps compute. (256,4) launch bounds -> <=64 regs, 4 blk/SM.
__global__ void __launch_bounds__(256, 4) k_gemm(int layer, const float* __restrict__ b) {
    __shared__ float4 Xs[2][512];        // [buf][node*8 + f]   8KB per buf
    __shared__ float4 Wsm[2][512];       // [buf][kq*64 + i]    8KB per buf
    int tid = threadIdx.x;
    int lane = tid & 31, warp = tid >> 5;
    int n0 = blockIdx.x * 64;
    int nb = warp * 8;
    const float4* Wt4 = (const float4*)(d_Wt + layer * 16384);
    const float4* F4 = (const float4*)d_F;

    unsigned int xs_s[2], ws_s[2];
    xs_s[0] = (unsigned int)__cvta_generic_to_shared(&Xs[0][0]);
    xs_s[1] = (unsigned int)__cvta_generic_to_shared(&Xs[1][0]);
    ws_s[0] = (unsigned int)__cvta_generic_to_shared(&Wsm[0][0]);
    ws_s[1] = (unsigned int)__cvta_generic_to_shared(&Wsm[1][0]);

    unsigned long long acc0[8], acc1[8];
#pragma unroll
    for (int n = 0; n < 8; n++) { acc0[n] = 0ull; acc1[n] = 0ull; }

    // stage chunk ch into buffer bf: X = 64 nodes x 8 float4, W = 8 kq x 64 float4
    auto stage = [&](int ch, int bf) {
#pragma unroll
        for (int t = 0; t < 2; t++) {
            int i = tid + t * 256;
            int n = i >> 3, f = i & 7;
            int node = n0 + n;
            if (node >= NN) node = NN - 1;        // clamp: no OOB cp.async
            cpa16(xs_s[bf] + i * 16, F4 + (size_t)node * 64 + ch * 8 + f);
        }
#pragma unroll
        for (int t = 0; t < 2; t++) {
            int i = tid + t * 256;
            cpa16(ws_s[bf] + i * 16, Wt4 + ch * 512 + i);
        }
        cpa_commit();
    };

    stage(0, 0);
    for (int ch = 0; ch < 8; ch++) {
        int bf = ch & 1;
        if (ch + 1 < 8) {
            stage(ch + 1, bf ^ 1);
            cpa_wait<1>();                        // chunk ch's group complete
        } else {
            cpa_wait<0>();
        }
        __syncthreads();                          // buf[bf] visible to all

        const ulonglong2* Ws2 = (const ulonglong2*)&Wsm[bf][0];
        const float* Xf = (const float*)&Xs[bf][0];
#pragma unroll
        for (int kq = 0; kq < 8; kq++) {
            ulonglong2 w0 = Ws2[kq * 64 + lane];          // conflict-free 512B
            ulonglong2 w1 = Ws2[kq * 64 + 32 + lane];
#pragma unroll
            for (int n = 0; n < 8; n++) {
                ulonglong2 x = *(const ulonglong2*)(Xf + (nb + n) * 32 + kq * 4); // broadcast
                ffma2(acc0[n], x.x, w0.x);
                ffma2(acc0[n], x.y, w0.y);
                ffma2(acc1[n], x.x, w1.x);
                ffma2(acc1[n], x.y, w1.y);
            }
        }
        __syncthreads();                          // done reading buf[bf] before re-stage
    }

    // epilogue: lane writes cols {lane, lane+32} of its warp's 8 nodes.
    float bias0 = __ldg(b + lane);
    float bias1 = __ldg(b + 32 + lane);
#pragma unroll
    for (int n = 0; n < 8; n++) {
        int node = n0 + nb + n;
        if (node < NN) {
            float l0, h0, l1, h1;
            upk2(acc0[n], l0, h0);
            upk2(acc1[n], l1, h1);
            float* row = d_F + (size_t)node * CD;
            row[lane]      = fmaxf(l0 + h0 + bias0, 0.f);
            row[32 + lane] = fmaxf(l1 + h1 + bias1, 0.f);
        }
    }
}

// ---------------------------------------------------------------------------
// Per-graph sums of F slot0 (graph_ids sorted -> running-accumulator flush)
__global__ void k_gsum(const int* __restrict__ gid) {
    const int CHN = 512;
    int c = threadIdx.x & 63;
    int r0 = threadIdx.x >> 6;
    int nbeg = blockIdx.x * CHN + r0;
    int nend = min(NN, blockIdx.x * CHN + CHN);
    float acc = 0.f;
    int cur = -1;
    for (int n = nbeg; n < nend; n += 4) {
        int g = gid[n];
        if (g != cur) {
            if (cur >= 0) atomicAdd(&d_gsum[cur * D + c], acc);
            cur = g; acc = 0.f;
        }
        acc += d_F[(size_t)n * CD + c];
    }
    if (cur >= 0) atomicAdd(&d_gsum[cur * D + c], acc);
}

// Readout: mean -> @embW + embb -> L2 normalize. One block, 256 threads.
__global__ void k_final(const int* __restrict__ gid,
                        const float* __restrict__ embW,
                        const float* __restrict__ embb,
                        float* __restrict__ out) {
    __shared__ float hg[NG][D];
    __shared__ int bnd[NG + 1];
    __shared__ float nrm[NG];
    int tid = threadIdx.x;

    if (tid <= NG) {
        int lo = 0, hi = NN;
        while (lo < hi) {
            int mid = (lo + hi) >> 1;
            if (gid[mid] < tid) lo = mid + 1; else hi = mid;
        }
        bnd[tid] = lo;
    }
    if (tid < NG) nrm[tid] = 0.f;
    __syncthreads();

    for (int idx = tid; idx < NG * D; idx += 256) {
        int g = idx >> 6;
        float cnt = (float)max(bnd[g + 1] - bnd[g], 1);
        hg[g][idx & 63] = d_gsum[idx] / cnt;
    }
    __syncthreads();

    for (int idx = tid; idx < NG * EMBD; idx += 256) {
        int g = idx >> 7, e = idx & 127;
        float s = embb[e];
#pragma unroll 16
        for (int k = 0; k < D; k++) s += hg[g][k] * embW[k * EMBD + e];
        atomicAdd(&nrm[g], s * s);
    }
    __syncthreads();

    for (int idx = tid; idx < NG * EMBD; idx += 256) {
        int g = idx >> 7, e = idx & 127;
        float s = embb[e];
#pragma unroll 16
        for (int k = 0; k < D; k++) s += hg[g][k] * embW[k * EMBD + e];
        float nv = fmaxf(sqrtf(nrm[g]), 1e-12f);
        out[idx] = s / nv;
    }
}

// ---------------------------------------------------------------------------
extern "C" void kernel_launch(void* const* d_in, const int* in_sizes, int n_in,
                              void* d_out, int out_size) {
    const float* h    = (const float*)d_in[0];
    const int*   src  = (const int*)d_in[1];
    const int*   dst  = (const int*)d_in[2];
    const int*   gid  = (const int*)d_in[3];
    const float* Wl[3] = {(const float*)d_in[4], (const float*)d_in[6], (const float*)d_in[8]};
    const float* bl[3] = {(const float*)d_in[5], (const float*)d_in[7], (const float*)d_in[9]};
    const float* embW = (const float*)d_in[10];
    const float* embb = (const float*)d_in[11];
    float* out = (float*)d_out;
    (void)in_sizes; (void)n_in; (void)out_size;

    k_prep0<<<(NN * 16 + 255) / 256, 256>>>(h, Wl[0], Wl[1], Wl[2]);  // 1
    k_prepB<<<PB, 256>>>(src, dst);                                   // 2

    for (int L = 0; L < 3; L++) {
        k_hops3<<<HB, 256>>>();                                       // 3 (L=0)
        k_gemm<<<(NN + 63) / 64, 256>>>(L, bl[L]);                    // 4 (L=0) <- profiled
    }

    k_gsum<<<(NN + 511) / 512, 256>>>(gid);
    k_final<<<1, 256>>>(gid, embW, embb, out);
}

// round 11
// speedup vs baseline: 1.9529x; 1.0049x over previous
#include <cuda_runtime.h>

#define NN   100000
#define EE   800000
#define D    64
#define CD   256          // (HOPS+1)*D
#define NG   64
#define EMBD 128
#define PB   512          // prepB persistent blocks ((256,4): >= 512 slots)
#define CH   196          // nodes per prepB chunk (512*196 >= NN)

// Persistent scratch
__device__ float d_F[(size_t)NN * CD];   // concat features [N][256]
__device__ float d_Wt[3 * 16384];        // permuted weights [L][kq][c][4k]
__device__ int   d_cnt[NN];
__device__ int   d_cur[NN];
__device__ int   d_off[NN + 1];
__device__ int   d_csr[EE];
__device__ int   d_bsum[PB];
__device__ float d_dn[NN];
__device__ float d_gsum[NG * D];
__device__ int   d_bar_cnt = 0;
__device__ int   d_bar_gen = 0;

// ---------------------------------------------------------------------------
__device__ __forceinline__ void upk2(unsigned long long v, float& lo, float& hi) {
    asm("mov.b64 {%0,%1}, %2;" : "=f"(lo), "=f"(hi) : "l"(v));
}
__device__ __forceinline__ void ffma2(unsigned long long& d, unsigned long long a,
                                      unsigned long long b) {
    asm("fma.rn.f32x2 %0, %1, %2, %0;" : "+l"(d) : "l"(a), "l"(b));
}
__device__ __forceinline__ void cpa16(unsigned int saddr, const void* gaddr) {
    asm volatile("cp.async.cg.shared.global [%0], [%1], 16;" :: "r"(saddr), "l"(gaddr));
}
__device__ __forceinline__ void cpa_commit() {
    asm volatile("cp.async.commit_group;");
}
template <int N> __device__ __forceinline__ void cpa_wait() {
    asm volatile("cp.async.wait_group %0;" :: "n"(N));
}

// Software grid barrier; all nblk blocks co-resident.
__device__ __forceinline__ void gbar(int nblk) {
    __threadfence();
    __syncthreads();
    if (threadIdx.x == 0) {
        int g = *((volatile int*)&d_bar_gen);
        int r = atomicAdd(&d_bar_cnt, 1);
        if (r == nblk - 1) {
            d_bar_cnt = 0;
            __threadfence();
            atomicAdd(&d_bar_gen, 1);
        } else {
            while (*((volatile int*)&d_bar_gen) == g) {}
        }
    }
    __syncthreads();
}

// ---------------------------------------------------------------------------
// prep0: copy h into F slot0, zero counters/gsum, permute W -> Wt [kq][c][4k]
__global__ void k_prep0(const float* __restrict__ h, const float* __restrict__ W0,
                        const float* __restrict__ W1, const float* __restrict__ W2) {
    int i = blockIdx.x * blockDim.x + threadIdx.x;
    if (i < NN * 16) {
        int r = i >> 4, p = i & 15;
        ((float4*)d_F)[(size_t)r * 64 + p] = ((const float4*)h)[i];
    }
    if (i < NN) { d_cnt[i] = 0; d_cur[i] = 0; }
    if (i < NG * D) d_gsum[i] = 0.f;
    if (i < 3 * 16384) {
        int L = i / 16384, gi = i - L * 16384;
        int kq = gi >> 8, r = gi & 255;
        int c = r >> 2, kk = r & 3;
        const float* W = (L == 0) ? W0 : (L == 1) ? W1 : W2;
        d_Wt[i] = W[(kq * 4 + kk) * 64 + c];
    }
}

// prepB (persistent): count -> scan(off,dn) -> CSR fill
__global__ void __launch_bounds__(256, 4) k_prepB(const int* __restrict__ src,
                                                  const int* __restrict__ dst) {
    __shared__ int sh[256];
    int tid = threadIdx.x, b = blockIdx.x;
    int gt = b * 256 + tid;
    const int GS = PB * 256;

    for (int e = gt; e < EE; e += GS) atomicAdd(&d_cnt[dst[e]], 1);
    gbar(PB);

    {   // per-block chunk sums
        int i0 = b * CH;
        int v = 0;
        if (tid < CH && i0 + tid < NN) v = d_cnt[i0 + tid];
        sh[tid] = v;
        __syncthreads();
        for (int st = 128; st > 0; st >>= 1) {
            if (tid < st) sh[tid] += sh[tid + st];
            __syncthreads();
        }
        if (tid == 0) d_bsum[b] = sh[0];
    }
    gbar(PB);

    {   // exclusive prefix + deg_norm
        int part = 0;
        for (int i = tid; i < b; i += 256) part += d_bsum[i];
        sh[tid] = part;
        __syncthreads();
        for (int st = 128; st > 0; st >>= 1) {
            if (tid < st) sh[tid] += sh[tid + st];
            __syncthreads();
        }
        int base = sh[0];
        __syncthreads();

        int i0 = b * CH, idx = i0 + tid;
        int v = (tid < CH && idx < NN) ? d_cnt[idx] : 0;
        sh[tid] = v;
        __syncthreads();
        for (int st = 1; st < 256; st <<= 1) {
            int a = (tid >= st) ? sh[tid - st] : 0;
            __syncthreads();
            sh[tid] += a;
            __syncthreads();
        }
        if (tid < CH && idx < NN) {
            d_off[idx] = base + sh[tid] - v;
            d_dn[idx] = rsqrtf(fmaxf((float)v, 1.0f));
        }
        if (gt == 0) d_off[NN] = EE;
    }
    gbar(PB);

    for (int e = gt; e < EE; e += GS) {
        int dd = dst[e];
        int p = atomicAdd(&d_cur[dd], 1);
        d_csr[d_off[dd] + p] = src[e];
    }
}

// ---------------------------------------------------------------------------
// Hop v2: half-warp (16 lanes x float4) per node; dual accumulator chains,
// 2 v-loads in flight, indices prefetched 2 ahead.
__global__ void __launch_bounds__(256) k_hop(int hop) {
    int node = blockIdx.x * 16 + (threadIdx.x >> 4);    // grid 6250*16 == NN
    int lane = threadIdx.x & 15;
    int e0 = __ldg(d_off + node);
    int e1 = __ldg(d_off + node + 1);
    const float4* F4 = (const float4*)d_F;
    int slot_in = (hop - 1) * 16 + lane;

    float4 accA = make_float4(0.f, 0.f, 0.f, 0.f);
    float4 accB = make_float4(0.f, 0.f, 0.f, 0.f);

    int s0 = 0, s1 = 0; float w0 = 0.f, w1 = 0.f;
    if (e0 < e1)     { s0 = __ldg(d_csr + e0);     w0 = __ldg(d_dn + s0); }
    if (e0 + 1 < e1) { s1 = __ldg(d_csr + e0 + 1); w1 = __ldg(d_dn + s1); }

    int e = e0;
    for (; e + 2 <= e1; e += 2) {
        int sn0 = 0, sn1 = 0; float wn0 = 0.f, wn1 = 0.f;
        if (e + 2 < e1) { sn0 = __ldg(d_csr + e + 2); wn0 = __ldg(d_dn + sn0); }
        if (e + 3 < e1) { sn1 = __ldg(d_csr + e + 3); wn1 = __ldg(d_dn + sn1); }
        float4 v0 = __ldg(F4 + (size_t)s0 * 64 + slot_in);
        float4 v1 = __ldg(F4 + (size_t)s1 * 64 + slot_in);
        accA.x = fmaf(v0.x, w0, accA.x); accA.y = fmaf(v0.y, w0, accA.y);
        accA.z = fmaf(v0.z, w0, accA.z); accA.w = fmaf(v0.w, w0, accA.w);
        accB.x = fmaf(v1.x, w1, accB.x); accB.y = fmaf(v1.y, w1, accB.y);
        accB.z = fmaf(v1.z, w1, accB.z); accB.w = fmaf(v1.w, w1, accB.w);
        s0 = sn0; w0 = wn0; s1 = sn1; w1 = wn1;
    }
    if (e < e1) {   // odd remainder: (s0, w0) holds edge e
        float4 v = __ldg(F4 + (size_t)s0 * 64 + slot_in);
        accA.x = fmaf(v.x, w0, accA.x); accA.y = fmaf(v.y, w0, accA.y);
        accA.z = fmaf(v.z, w0, accA.z); accA.w = fmaf(v.w, w0, accA.w);
    }

    float dn = __ldg(d_dn + node);
    float4 acc;
    acc.x = (accA.x + accB.x) * dn;
    acc.y = (accA.y + accB.y) * dn;
    acc.z = (accA.z + accB.z) * dn;
    acc.w = (accA.w + accB.w) * dn;
    ((float4*)d_F)[(size_t)node * 64 + hop * 16 + lane] = acc;
}

// ---------------------------------------------------------------------------
// GEMM v7 (measured 95us): block = 64 nodes; warp = 8 nodes x 64 cols; lane
// owns cols {lane, lane+32}. K chunked x8; X and W double-buffered cp.async.
__global__ void __launch_bounds__(256, 4) k_gemm(int layer, const float* __restrict__ b) {
    __shared__ float4 Xs[2][512];        // [buf][node*8 + f]   8KB per buf
    __shared__ float4 Wsm[2][512];       // [buf][kq*64 + i]    8KB per buf
    int tid = threadIdx.x;
    int lane = tid & 31, warp = tid >> 5;
    int n0 = blockIdx.x * 64;
    int nb = warp * 8;
    const float4* Wt4 = (const float4*)(d_Wt + layer * 16384);
    const float4* F4 = (const float4*)d_F;

    unsigned int xs_s[2], ws_s[2];
    xs_s[0] = (unsigned int)__cvta_generic_to_shared(&Xs[0][0]);
    xs_s[1] = (unsigned int)__cvta_generic_to_shared(&Xs[1][0]);
    ws_s[0] = (unsigned int)__cvta_generic_to_shared(&Wsm[0][0]);
    ws_s[1] = (unsigned int)__cvta_generic_to_shared(&Wsm[1][0]);

    unsigned long long acc0[8], acc1[8];
#pragma unroll
    for (int n = 0; n < 8; n++) { acc0[n] = 0ull; acc1[n] = 0ull; }

    auto stage = [&](int ch, int bf) {
#pragma unroll
        for (int t = 0; t < 2; t++) {
            int i = tid + t * 256;
            int n = i >> 3, f = i & 7;
            int node = n0 + n;
            if (node >= NN) node = NN - 1;        // clamp: no OOB cp.async
            cpa16(xs_s[bf] + i * 16, F4 + (size_t)node * 64 + ch * 8 + f);
        }
#pragma unroll
        for (int t = 0; t < 2; t++) {
            int i = tid + t * 256;
            cpa16(ws_s[bf] + i * 16, Wt4 + ch * 512 + i);
        }
        cpa_commit();
    };

    stage(0, 0);
    for (int ch = 0; ch < 8; ch++) {
        int bf = ch & 1;
        if (ch + 1 < 8) {
            stage(ch + 1, bf ^ 1);
            cpa_wait<1>();
        } else {
            cpa_wait<0>();
        }
        __syncthreads();

        const ulonglong2* Ws2 = (const ulonglong2*)&Wsm[bf][0];
        const float* Xf = (const float*)&Xs[bf][0];
#pragma unroll
        for (int kq = 0; kq < 8; kq++) {
            ulonglong2 w0 = Ws2[kq * 64 + lane];
            ulonglong2 w1 = Ws2[kq * 64 + 32 + lane];
#pragma unroll
            for (int n = 0; n < 8; n++) {
                ulonglong2 x = *(const ulonglong2*)(Xf + (nb + n) * 32 + kq * 4);
                ffma2(acc0[n], x.x, w0.x);
                ffma2(acc0[n], x.y, w0.y);
                ffma2(acc1[n], x.x, w1.x);
                ffma2(acc1[n], x.y, w1.y);
            }
        }
        __syncthreads();
    }

    float bias0 = __ldg(b + lane);
    float bias1 = __ldg(b + 32 + lane);
#pragma unroll
    for (int n = 0; n < 8; n++) {
        int node = n0 + nb + n;
        if (node < NN) {
            float l0, h0, l1, h1;
            upk2(acc0[n], l0, h0);
            upk2(acc1[n], l1, h1);
            float* row = d_F + (size_t)node * CD;
            row[lane]      = fmaxf(l0 + h0 + bias0, 0.f);
            row[32 + lane] = fmaxf(l1 + h1 + bias1, 0.f);
        }
    }
}

// ---------------------------------------------------------------------------
// Per-graph sums of F slot0 (graph_ids sorted -> running-accumulator flush)
__global__ void k_gsum(const int* __restrict__ gid) {
    const int CHN = 512;
    int c = threadIdx.x & 63;
    int r0 = threadIdx.x >> 6;
    int nbeg = blockIdx.x * CHN + r0;
    int nend = min(NN, blockIdx.x * CHN + CHN);
    float acc = 0.f;
    int cur = -1;
    for (int n = nbeg; n < nend; n += 4) {
        int g = gid[n];
        if (g != cur) {
            if (cur >= 0) atomicAdd(&d_gsum[cur * D + c], acc);
            cur = g; acc = 0.f;
        }
        acc += d_F[(size_t)n * CD + c];
    }
    if (cur >= 0) atomicAdd(&d_gsum[cur * D + c], acc);
}

// Readout: mean -> @embW + embb -> L2 normalize. One block, 256 threads.
__global__ void k_final(const int* __restrict__ gid,
                        const float* __restrict__ embW,
                        const float* __restrict__ embb,
                        float* __restrict__ out) {
    __shared__ float hg[NG][D];
    __shared__ int bnd[NG + 1];
    __shared__ float nrm[NG];
    int tid = threadIdx.x;

    if (tid <= NG) {
        int lo = 0, hi = NN;
        while (lo < hi) {
            int mid = (lo + hi) >> 1;
            if (gid[mid] < tid) lo = mid + 1; else hi = mid;
        }
        bnd[tid] = lo;
    }
    if (tid < NG) nrm[tid] = 0.f;
    __syncthreads();

    for (int idx = tid; idx < NG * D; idx += 256) {
        int g = idx >> 6;
        float cnt = (float)max(bnd[g + 1] - bnd[g], 1);
        hg[g][idx & 63] = d_gsum[idx] / cnt;
    }
    __syncthreads();

    for (int idx = tid; idx < NG * EMBD; idx += 256) {
        int g = idx >> 7, e = idx & 127;
        float s = embb[e];
#pragma unroll 16
        for (int k = 0; k < D; k++) s += hg[g][k] * embW[k * EMBD + e];
        atomicAdd(&nrm[g], s * s);
    }
    __syncthreads();

    for (int idx = tid; idx < NG * EMBD; idx += 256) {
        int g = idx >> 7, e = idx & 127;
        float s = embb[e];
#pragma unroll 16
        for (int k = 0; k < D; k++) s += hg[g][k] * embW[k * EMBD + e];
        float nv = fmaxf(sqrtf(nrm[g]), 1e-12f);
        out[idx] = s / nv;
    }
}

// ---------------------------------------------------------------------------
extern "C" void kernel_launch(void* const* d_in, const int* in_sizes, int n_in,
                              void* d_out, int out_size) {
    const float* h    = (const float*)d_in[0];
    const int*   src  = (const int*)d_in[1];
    const int*   dst  = (const int*)d_in[2];
    const int*   gid  = (const int*)d_in[3];
    const float* Wl[3] = {(const float*)d_in[4], (const float*)d_in[6], (const float*)d_in[8]};
    const float* bl[3] = {(const float*)d_in[5], (const float*)d_in[7], (const float*)d_in[9]};
    const float* embW = (const float*)d_in[10];
    const float* embb = (const float*)d_in[11];
    float* out = (float*)d_out;
    (void)in_sizes; (void)n_in; (void)out_size;

    k_prep0<<<(NN * 16 + 255) / 256, 256>>>(h, Wl[0], Wl[1], Wl[2]);  // 1
    k_prepB<<<PB, 256>>>(src, dst);                                   // 2

    for (int L = 0; L < 3; L++) {
        k_hop<<<NN / 16, 256>>>(1);                                   // 3 (L=0)
        k_hop<<<NN / 16, 256>>>(2);                                   // 4 (L=0) <- profiled
        k_hop<<<NN / 16, 256>>>(3);
        k_gemm<<<(NN + 63) / 64, 256>>>(L, bl[L]);
    }

    k_gsum<<<(NN + 511) / 512, 256>>>(gid);
    k_final<<<1, 256>>>(gid, embW, embb, out);
}

// round 12
// speedup vs baseline: 2.0381x; 1.0436x over previous
#include <cuda_runtime.h>

#define NN   100000
#define EE   800000
#define D    64
#define CD   256          // (HOPS+1)*D
#define NG   64
#define EMBD 128
#define PB   512          // prepB persistent blocks ((256,4): >= 512 slots)
#define CH   196          // nodes per prepB chunk (512*196 >= NN)

// Persistent scratch
__device__ float d_F[(size_t)NN * CD];   // concat features [N][256]
__device__ float d_Wt[3 * 16384];        // permuted weights [L][kq][c][4k]
__device__ int   d_cnt[NN];
__device__ int   d_cur[NN];
__device__ int   d_off[NN + 1];
__device__ int2  d_csrw[EE];             // per-edge {src, dn[src] bits}
__device__ int   d_bsum[PB];
__device__ float d_dn[NN];
__device__ float d_gsum[NG * D];
__device__ int   d_bar_cnt = 0;
__device__ int   d_bar_gen = 0;

// ---------------------------------------------------------------------------
__device__ __forceinline__ void upk2(unsigned long long v, float& lo, float& hi) {
    asm("mov.b64 {%0,%1}, %2;" : "=f"(lo), "=f"(hi) : "l"(v));
}
__device__ __forceinline__ void ffma2(unsigned long long& d, unsigned long long a,
                                      unsigned long long b) {
    asm("fma.rn.f32x2 %0, %1, %2, %0;" : "+l"(d) : "l"(a), "l"(b));
}
__device__ __forceinline__ void cpa16(unsigned int saddr, const void* gaddr) {
    asm volatile("cp.async.cg.shared.global [%0], [%1], 16;" :: "r"(saddr), "l"(gaddr));
}
__device__ __forceinline__ void cpa_commit() {
    asm volatile("cp.async.commit_group;");
}
template <int N> __device__ __forceinline__ void cpa_wait() {
    asm volatile("cp.async.wait_group %0;" :: "n"(N));
}

// Software grid barrier; all nblk blocks co-resident.
__device__ __forceinline__ void gbar(int nblk) {
    __threadfence();
    __syncthreads();
    if (threadIdx.x == 0) {
        int g = *((volatile int*)&d_bar_gen);
        int r = atomicAdd(&d_bar_cnt, 1);
        if (r == nblk - 1) {
            d_bar_cnt = 0;
            __threadfence();
            atomicAdd(&d_bar_gen, 1);
        } else {
            while (*((volatile int*)&d_bar_gen) == g) {}
        }
    }
    __syncthreads();
}

// ---------------------------------------------------------------------------
// prep0: copy h into F slot0, zero counters/gsum, permute W -> Wt [kq][c][4k]
__global__ void k_prep0(const float* __restrict__ h, const float* __restrict__ W0,
                        const float* __restrict__ W1, const float* __restrict__ W2) {
    int i = blockIdx.x * blockDim.x + threadIdx.x;
    if (i < NN * 16) {
        int r = i >> 4, p = i & 15;
        ((float4*)d_F)[(size_t)r * 64 + p] = ((const float4*)h)[i];
    }
    if (i < NN) { d_cnt[i] = 0; d_cur[i] = 0; }
    if (i < NG * D) d_gsum[i] = 0.f;
    if (i < 3 * 16384) {
        int L = i / 16384, gi = i - L * 16384;
        int kq = gi >> 8, r = gi & 255;
        int c = r >> 2, kk = r & 3;
        const float* W = (L == 0) ? W0 : (L == 1) ? W1 : W2;
        d_Wt[i] = W[(kq * 4 + kk) * 64 + c];
    }
}

// prepB (persistent): count -> scan(off,dn) -> CSR fill with fused {src, dn[src]}
__global__ void __launch_bounds__(256, 4) k_prepB(const int* __restrict__ src,
                                                  const int* __restrict__ dst) {
    __shared__ int sh[256];
    int tid = threadIdx.x, b = blockIdx.x;
    int gt = b * 256 + tid;
    const int GS = PB * 256;

    for (int e = gt; e < EE; e += GS) atomicAdd(&d_cnt[dst[e]], 1);
    gbar(PB);

    {   // per-block chunk sums
        int i0 = b * CH;
        int v = 0;
        if (tid < CH && i0 + tid < NN) v = d_cnt[i0 + tid];
        sh[tid] = v;
        __syncthreads();
        for (int st = 128; st > 0; st >>= 1) {
            if (tid < st) sh[tid] += sh[tid + st];
            __syncthreads();
        }
        if (tid == 0) d_bsum[b] = sh[0];
    }
    gbar(PB);

    {   // exclusive prefix + deg_norm
        int part = 0;
        for (int i = tid; i < b; i += 256) part += d_bsum[i];
        sh[tid] = part;
        __syncthreads();
        for (int st = 128; st > 0; st >>= 1) {
            if (tid < st) sh[tid] += sh[tid + st];
            __syncthreads();
        }
        int base = sh[0];
        __syncthreads();

        int i0 = b * CH, idx = i0 + tid;
        int v = (tid < CH && idx < NN) ? d_cnt[idx] : 0;
        sh[tid] = v;
        __syncthreads();
        for (int st = 1; st < 256; st <<= 1) {
            int a = (tid >= st) ? sh[tid - st] : 0;
            __syncthreads();
            sh[tid] += a;
            __syncthreads();
        }
        if (tid < CH && idx < NN) {
            d_off[idx] = base + sh[tid] - v;
            d_dn[idx] = rsqrtf(fmaxf((float)v, 1.0f));
        }
        if (gt == 0) d_off[NN] = EE;
    }
    gbar(PB);

    for (int e = gt; e < EE; e += GS) {
        int dd = dst[e];
        int s = src[e];
        int p = atomicAdd(&d_cur[dd], 1);
        d_csrw[d_off[dd] + p] = make_int2(s, __float_as_int(d_dn[s]));
    }
}

// ---------------------------------------------------------------------------
// Hop v3: half-warp (16 lanes x float4) per node; fused {src,w} edge records
// (4 LDG per 2 edges instead of 6), dual accumulator chains.
__global__ void __launch_bounds__(256) k_hop(int hop) {
    int node = blockIdx.x * 16 + (threadIdx.x >> 4);    // grid 6250*16 == NN
    int lane = threadIdx.x & 15;
    int e0 = __ldg(d_off + node);
    int e1 = __ldg(d_off + node + 1);
    const float4* F4 = (const float4*)d_F;
    int slot_in = (hop - 1) * 16 + lane;

    float4 accA = make_float4(0.f, 0.f, 0.f, 0.f);
    float4 accB = make_float4(0.f, 0.f, 0.f, 0.f);

    int2 p0 = make_int2(0, 0), p1 = make_int2(0, 0);
    if (e0 < e1)     p0 = __ldg(d_csrw + e0);
    if (e0 + 1 < e1) p1 = __ldg(d_csrw + e0 + 1);

    int e = e0;
    for (; e + 2 <= e1; e += 2) {
        int2 pn0 = make_int2(0, 0), pn1 = make_int2(0, 0);
        if (e + 2 < e1) pn0 = __ldg(d_csrw + e + 2);
        if (e + 3 < e1) pn1 = __ldg(d_csrw + e + 3);
        float w0 = __int_as_float(p0.y);
        float w1 = __int_as_float(p1.y);
        float4 v0 = __ldg(F4 + (size_t)p0.x * 64 + slot_in);
        float4 v1 = __ldg(F4 + (size_t)p1.x * 64 + slot_in);
        accA.x = fmaf(v0.x, w0, accA.x); accA.y = fmaf(v0.y, w0, accA.y);
        accA.z = fmaf(v0.z, w0, accA.z); accA.w = fmaf(v0.w, w0, accA.w);
        accB.x = fmaf(v1.x, w1, accB.x); accB.y = fmaf(v1.y, w1, accB.y);
        accB.z = fmaf(v1.z, w1, accB.z); accB.w = fmaf(v1.w, w1, accB.w);
        p0 = pn0; p1 = pn1;
    }
    if (e < e1) {   // odd remainder: p0 holds edge e
        float w = __int_as_float(p0.y);
        float4 v = __ldg(F4 + (size_t)p0.x * 64 + slot_in);
        accA.x = fmaf(v.x, w, accA.x); accA.y = fmaf(v.y, w, accA.y);
        accA.z = fmaf(v.z, w, accA.z); accA.w = fmaf(v.w, w, accA.w);
    }

    float dn = __ldg(d_dn + node);
    float4 acc;
    acc.x = (accA.x + accB.x) * dn;
    acc.y = (accA.y + accB.y) * dn;
    acc.z = (accA.z + accB.z) * dn;
    acc.w = (accA.w + accB.w) * dn;
    ((float4*)d_F)[(size_t)node * 64 + hop * 16 + lane] = acc;
}

// ---------------------------------------------------------------------------
// GEMM v8: 128 threads / 4 warps; warp = 16 nodes x 64 cols (lane owns cols
// {lane, lane+32}); block = 64 nodes. K chunked x8, X/W double-buffered
// cp.async. Crossbar/warp/kq = 24 cyc vs FFMA2 128 -> FFMA2-bound (~80%).
__global__ void __launch_bounds__(128, 4) k_gemm(int layer, const float* __restrict__ b) {
    __shared__ float4 Xs[2][512];        // [buf][node*8 + f]   8KB per buf
    __shared__ float4 Wsm[2][512];       // [buf][kq*64 + i]    8KB per buf
    int tid = threadIdx.x;
    int lane = tid & 31, warp = tid >> 5;
    int n0 = blockIdx.x * 64;
    int nb = warp * 16;                  // warp's 16 nodes within the block
    const float4* Wt4 = (const float4*)(d_Wt + layer * 16384);
    const float4* F4 = (const float4*)d_F;

    unsigned int xs_s[2], ws_s[2];
    xs_s[0] = (unsigned int)__cvta_generic_to_shared(&Xs[0][0]);
    xs_s[1] = (unsigned int)__cvta_generic_to_shared(&Xs[1][0]);
    ws_s[0] = (unsigned int)__cvta_generic_to_shared(&Wsm[0][0]);
    ws_s[1] = (unsigned int)__cvta_generic_to_shared(&Wsm[1][0]);

    unsigned long long acc0[16], acc1[16];
#pragma unroll
    for (int n = 0; n < 16; n++) { acc0[n] = 0ull; acc1[n] = 0ull; }

    auto stage = [&](int ch, int bf) {
#pragma unroll
        for (int t = 0; t < 4; t++) {
            int i = tid + t * 128;
            int n = i >> 3, f = i & 7;
            int node = n0 + n;
            if (node >= NN) node = NN - 1;        // clamp: no OOB cp.async
            cpa16(xs_s[bf] + i * 16, F4 + (size_t)node * 64 + ch * 8 + f);
        }
#pragma unroll
        for (int t = 0; t < 4; t++) {
            int i = tid + t * 128;
            cpa16(ws_s[bf] + i * 16, Wt4 + ch * 512 + i);
        }
        cpa_commit();
    };

    stage(0, 0);
    for (int ch = 0; ch < 8; ch++) {
        int bf = ch & 1;
        if (ch + 1 < 8) {
            stage(ch + 1, bf ^ 1);
            cpa_wait<1>();
        } else {
            cpa_wait<0>();
        }
        __syncthreads();

        const ulonglong2* Ws2 = (const ulonglong2*)&Wsm[bf][0];
        const float* Xf = (const float*)&Xs[bf][0];
#pragma unroll
        for (int kq = 0; kq < 8; kq++) {
            ulonglong2 w0 = Ws2[kq * 64 + lane];          // 512B contig, conflict-free
            ulonglong2 w1 = Ws2[kq * 64 + 32 + lane];
#pragma unroll
            for (int n = 0; n < 16; n++) {
                ulonglong2 x = *(const ulonglong2*)(Xf + (nb + n) * 32 + kq * 4); // bcast
                ffma2(acc0[n], x.x, w0.x);
                ffma2(acc0[n], x.y, w0.y);
                ffma2(acc1[n], x.x, w1.x);
                ffma2(acc1[n], x.y, w1.y);
            }
        }
        __syncthreads();
    }

    float bias0 = __ldg(b + lane);
    float bias1 = __ldg(b + 32 + lane);
#pragma unroll
    for (int n = 0; n < 16; n++) {
        int node = n0 + nb + n;
        if (node < NN) {
            float l0, h0, l1, h1;
            upk2(acc0[n], l0, h0);
            upk2(acc1[n], l1, h1);
            float* row = d_F + (size_t)node * CD;
            row[lane]      = fmaxf(l0 + h0 + bias0, 0.f);
            row[32 + lane] = fmaxf(l1 + h1 + bias1, 0.f);
        }
    }
}

// ---------------------------------------------------------------------------
// Per-graph sums of F slot0 (graph_ids sorted -> running-accumulator flush)
__global__ void k_gsum(const int* __restrict__ gid) {
    const int CHN = 512;
    int c = threadIdx.x & 63;
    int r0 = threadIdx.x >> 6;
    int nbeg = blockIdx.x * CHN + r0;
    int nend = min(NN, blockIdx.x * CHN + CHN);
    float acc = 0.f;
    int cur = -1;
    for (int n = nbeg; n < nend; n += 4) {
        int g = gid[n];
        if (g != cur) {
            if (cur >= 0) atomicAdd(&d_gsum[cur * D + c], acc);
            cur = g; acc = 0.f;
        }
        acc += d_F[(size_t)n * CD + c];
    }
    if (cur >= 0) atomicAdd(&d_gsum[cur * D + c], acc);
}

// Readout: mean -> @embW + embb -> L2 normalize. One block, 256 threads.
__global__ void k_final(const int* __restrict__ gid,
                        const float* __restrict__ embW,
                        const float* __restrict__ embb,
                        float* __restrict__ out) {
    __shared__ float hg[NG][D];
    __shared__ int bnd[NG + 1];
    __shared__ float nrm[NG];
    int tid = threadIdx.x;

    if (tid <= NG) {
        int lo = 0, hi = NN;
        while (lo < hi) {
            int mid = (lo + hi) >> 1;
            if (gid[mid] < tid) lo = mid + 1; else hi = mid;
        }
        bnd[tid] = lo;
    }
    if (tid < NG) nrm[tid] = 0.f;
    __syncthreads();

    for (int idx = tid; idx < NG * D; idx += 256) {
        int g = idx >> 6;
        float cnt = (float)max(bnd[g + 1] - bnd[g], 1);
        hg[g][idx & 63] = d_gsum[idx] / cnt;
    }
    __syncthreads();

    for (int idx = tid; idx < NG * EMBD; idx += 256) {
        int g = idx >> 7, e = idx & 127;
        float s = embb[e];
#pragma unroll 16
        for (int k = 0; k < D; k++) s += hg[g][k] * embW[k * EMBD + e];
        atomicAdd(&nrm[g], s * s);
    }
    __syncthreads();

    for (int idx = tid; idx < NG * EMBD; idx += 256) {
        int g = idx >> 7, e = idx & 127;
        float s = embb[e];
#pragma unroll 16
        for (int k = 0; k < D; k++) s += hg[g][k] * embW[k * EMBD + e];
        float nv = fmaxf(sqrtf(nrm[g]), 1e-12f);
        out[idx] = s / nv;
    }
}

// ---------------------------------------------------------------------------
extern "C" void kernel_launch(void* const* d_in, const int* in_sizes, int n_in,
                              void* d_out, int out_size) {
    const float* h    = (const float*)d_in[0];
    const int*   src  = (const int*)d_in[1];
    const int*   dst  = (const int*)d_in[2];
    const int*   gid  = (const int*)d_in[3];
    const float* Wl[3] = {(const float*)d_in[4], (const float*)d_in[6], (const float*)d_in[8]};
    const float* bl[3] = {(const float*)d_in[5], (const float*)d_in[7], (const float*)d_in[9]};
    const float* embW = (const float*)d_in[10];
    const float* embb = (const float*)d_in[11];
    float* out = (float*)d_out;
    (void)in_sizes; (void)n_in; (void)out_size;

    k_prep0<<<(NN * 16 + 255) / 256, 256>>>(h, Wl[0], Wl[1], Wl[2]);  // 1
    k_prepB<<<PB, 256>>>(src, dst);                                   // 2

    for (int L = 0; L < 3; L++) {
        k_hop<<<NN / 16, 256>>>(1);                                   // 3 (L=0)
        k_hop<<<NN / 16, 256>>>(2);                                   // 4 (L=0) <- profiled
        k_hop<<<NN / 16, 256>>>(3);
        k_gemm<<<(NN + 63) / 64, 128>>>(L, bl[L]);
    }

    k_gsum<<<(NN + 511) / 512, 256>>>(gid);
    k_final<<<1, 256>>>(gid, embW, embb, out);
}